// round 1
// baseline (speedup 1.0000x reference)
#include <cuda_runtime.h>
#include <math.h>

#define N_NODES   50000
#define N_EDGES   800000
#define TOT_EDGES (N_EDGES + N_NODES)
#define HEADS     4
#define OUT_CH    64
#define DHID      256   // HEADS * OUT_CH
#define KDIM      256   // input feature dim for both layers

// ---------------- scratch (static device globals; no allocation) ------------
__device__ float g_h[N_NODES * DHID];       // post-GEMM features [N, H, C]
__device__ float g_act[N_NODES * DHID];     // layer-1 output after ELU
__device__ float g_out[N_NODES * DHID];     // aggregation accumulator
__device__ float g_asrc[N_NODES * HEADS];
__device__ float g_adst[N_NODES * HEADS];
__device__ float g_denom[N_NODES * HEADS];
__device__ float g_eexp[TOT_EDGES * HEADS];

// vector reduction to global (sm_90+)
__device__ __forceinline__ void red_add_v4(float* addr, float4 v) {
    asm volatile("red.global.add.v4.f32 [%0], {%1, %2, %3, %4};"
                 :: "l"(addr), "f"(v.x), "f"(v.y), "f"(v.z), "f"(v.w)
                 : "memory");
}

// ---------------- zero accumulator + denom ----------------------------------
__global__ void zero_kernel() {
    int i = blockIdx.x * blockDim.x + threadIdx.x;
    const int NOUT4 = N_NODES * DHID / 4;    // 3,200,000
    const int NDEN4 = N_NODES * HEADS / 4;   // 50,000
    float4 z = make_float4(0.f, 0.f, 0.f, 0.f);
    if (i < NOUT4) ((float4*)g_out)[i] = z;
    if (i < NDEN4) ((float4*)g_denom)[i] = z;
}

// ---------------- SGEMM: g_h = A[M,256] @ B[256,256] ------------------------
// BM=128, BN=64, BK=16, 256 threads, 8x4 per thread
__global__ __launch_bounds__(256) void sgemm_kernel(
    const float* __restrict__ Aext, const float* __restrict__ B, int use_act)
{
    const float* A = use_act ? (const float*)g_act : Aext;
    __shared__ float As[16][128];
    __shared__ float Bs[16][64];

    int bm = blockIdx.x * 128;
    int bn = blockIdx.y * 64;
    int t  = threadIdx.x;
    int tx = t & 15;        // 0..15 -> 4 cols
    int ty = t >> 4;        // 0..15 -> 8 rows

    int arow = t >> 2;          // 0..63
    int acg  = (t & 3) * 4;     // 0,4,8,12
    int brow = t >> 4;          // 0..15
    int bcol = (t & 15) * 4;    // 0..60

    float acc[8][4];
    #pragma unroll
    for (int i = 0; i < 8; i++)
        #pragma unroll
        for (int j = 0; j < 4; j++) acc[i][j] = 0.f;

    for (int k0 = 0; k0 < KDIM; k0 += 16) {
        #pragma unroll
        for (int i = 0; i < 2; i++) {
            int r  = arow + i * 64;
            int gr = bm + r;
            float4 v = make_float4(0.f, 0.f, 0.f, 0.f);
            if (gr < N_NODES) v = *(const float4*)&A[(long)gr * KDIM + k0 + acg];
            As[acg + 0][r] = v.x;
            As[acg + 1][r] = v.y;
            As[acg + 2][r] = v.z;
            As[acg + 3][r] = v.w;
        }
        {
            float4 v = *(const float4*)&B[(long)(k0 + brow) * DHID + bn + bcol];
            *(float4*)&Bs[brow][bcol] = v;
        }
        __syncthreads();

        #pragma unroll
        for (int k = 0; k < 16; k++) {
            float4 a0 = *(const float4*)&As[k][ty * 8];
            float4 a1 = *(const float4*)&As[k][ty * 8 + 4];
            float4 b0 = *(const float4*)&Bs[k][tx * 4];
            float ar[8] = {a0.x, a0.y, a0.z, a0.w, a1.x, a1.y, a1.z, a1.w};
            float br[4] = {b0.x, b0.y, b0.z, b0.w};
            #pragma unroll
            for (int i = 0; i < 8; i++)
                #pragma unroll
                for (int j = 0; j < 4; j++)
                    acc[i][j] += ar[i] * br[j];
        }
        __syncthreads();
    }

    #pragma unroll
    for (int i = 0; i < 8; i++) {
        int gr = bm + ty * 8 + i;
        if (gr < N_NODES) {
            float4 v = make_float4(acc[i][0], acc[i][1], acc[i][2], acc[i][3]);
            *(float4*)&g_h[(long)gr * DHID + bn + tx * 4] = v;
        }
    }
}

// ---------------- attention scores: a_src/a_dst [N, H] ----------------------
// one warp per (node, head)
__global__ void attn_kernel(const float* __restrict__ att_src,
                            const float* __restrict__ att_dst)
{
    int gw   = (blockIdx.x * blockDim.x + threadIdx.x) >> 5;
    int lane = threadIdx.x & 31;
    if (gw >= N_NODES * HEADS) return;
    int n  = gw >> 2;
    int hd = gw & 3;
    const float* hp = &g_h[(long)n * DHID + hd * OUT_CH];
    const float* as = &att_src[hd * OUT_CH];
    const float* ad = &att_dst[hd * OUT_CH];
    float h0 = hp[lane], h1 = hp[lane + 32];
    float s = h0 * as[lane] + h1 * as[lane + 32];
    float d = h0 * ad[lane] + h1 * ad[lane + 32];
    #pragma unroll
    for (int o = 16; o > 0; o >>= 1) {
        s += __shfl_xor_sync(0xFFFFFFFFu, s, o);
        d += __shfl_xor_sync(0xFFFFFFFFu, d, o);
    }
    if (lane == 0) { g_asrc[gw] = s; g_adst[gw] = d; }
}

// ---------------- edge pass 1: e_exp + denom (softmax w/o max shift) --------
__global__ void edge_softmax_kernel(const int* __restrict__ ei)
{
    int i = blockIdx.x * blockDim.x + threadIdx.x;
    if (i >= TOT_EDGES) return;
    int s, d;
    if (i < N_EDGES) { s = ei[i]; d = ei[N_EDGES + i]; }
    else             { s = d = i - N_EDGES; }   // self loops

    float4 a = *(const float4*)&g_asrc[s * 4];
    float4 b = *(const float4*)&g_adst[d * 4];
    float4 e;
    e.x = a.x + b.x; e.y = a.y + b.y; e.z = a.z + b.z; e.w = a.w + b.w;
    // leaky relu (0.2), then exp
    e.x = (e.x > 0.f) ? e.x : 0.2f * e.x;
    e.y = (e.y > 0.f) ? e.y : 0.2f * e.y;
    e.z = (e.z > 0.f) ? e.z : 0.2f * e.z;
    e.w = (e.w > 0.f) ? e.w : 0.2f * e.w;
    e.x = __expf(e.x); e.y = __expf(e.y); e.z = __expf(e.z); e.w = __expf(e.w);

    *(float4*)&g_eexp[(long)i * 4] = e;
    red_add_v4(&g_denom[d * 4], e);
}

// ---------------- edge pass 2: out[dst] += alpha * h[src] -------------------
// one warp per edge; each lane handles 8 contiguous channels (one head each)
__global__ void edge_aggregate_kernel(const int* __restrict__ ei)
{
    int warp = (blockIdx.x * blockDim.x + threadIdx.x) >> 5;
    int lane = threadIdx.x & 31;
    if (warp >= TOT_EDGES) return;
    int s, d;
    if (warp < N_EDGES) { s = ei[warp]; d = ei[N_EDGES + warp]; }
    else                { s = d = warp - N_EDGES; }

    int head = lane >> 3;                     // 8 lanes per head
    float num   = g_eexp[(long)warp * 4 + head];
    float den   = g_denom[d * 4 + head];
    float alpha = num / (den + 1e-16f);

    const float4* hp = (const float4*)&g_h[(long)s * DHID + lane * 8];
    float4 v0 = hp[0];
    float4 v1 = hp[1];
    v0.x *= alpha; v0.y *= alpha; v0.z *= alpha; v0.w *= alpha;
    v1.x *= alpha; v1.y *= alpha; v1.z *= alpha; v1.w *= alpha;

    float* op = &g_out[(long)d * DHID + lane * 8];
    red_add_v4(op, v0);
    red_add_v4(op + 4, v1);
}

// ---------------- epilogue: dst = ELU(out + bias) ---------------------------
__global__ void epilogue_kernel(const float* __restrict__ bias,
                                float* __restrict__ dst_ext, int to_act)
{
    int i = blockIdx.x * blockDim.x + threadIdx.x;
    const int TOT4 = N_NODES * DHID / 4;
    if (i >= TOT4) return;
    float* dst = to_act ? (float*)g_act : dst_ext;
    float4 v = ((const float4*)g_out)[i];
    float4 bz = ((const float4*)bias)[i & 63];   // 64 float4 per row
    v.x += bz.x; v.y += bz.y; v.z += bz.z; v.w += bz.w;
    v.x = (v.x > 0.f) ? v.x : expm1f(v.x);
    v.y = (v.y > 0.f) ? v.y : expm1f(v.y);
    v.z = (v.z > 0.f) ? v.z : expm1f(v.z);
    v.w = (v.w > 0.f) ? v.w : expm1f(v.w);
    ((float4*)dst)[i] = v;
}

// ---------------- launch ----------------------------------------------------
extern "C" void kernel_launch(void* const* d_in, const int* in_sizes, int n_in,
                              void* d_out, int out_size)
{
    const float* x   = (const float*)d_in[0];
    const int*   ei  = (const int*)  d_in[1];
    const float* W1  = (const float*)d_in[2];
    const float* as1 = (const float*)d_in[3];
    const float* ad1 = (const float*)d_in[4];
    const float* b1  = (const float*)d_in[5];
    const float* W2  = (const float*)d_in[6];
    const float* as2 = (const float*)d_in[7];
    const float* ad2 = (const float*)d_in[8];
    const float* b2  = (const float*)d_in[9];
    float* out = (float*)d_out;

    dim3 gemm_grid((N_NODES + 127) / 128, DHID / 64);
    int zero_blocks = (N_NODES * DHID / 4 + 255) / 256;           // 12500
    int attn_blocks = (N_NODES * HEADS + 7) / 8;                  // 25000 (8 warps/blk)
    int e1_blocks   = (TOT_EDGES + 255) / 256;                    // 3321
    int e2_blocks   = (TOT_EDGES * 32 + 255) / 256;               // 106250
    int epi_blocks  = zero_blocks;

    // ---------------- layer 1 ----------------
    zero_kernel<<<zero_blocks, 256>>>();
    sgemm_kernel<<<gemm_grid, 256>>>(x, W1, 0);
    attn_kernel<<<attn_blocks, 256>>>(as1, ad1);
    edge_softmax_kernel<<<e1_blocks, 256>>>(ei);
    edge_aggregate_kernel<<<e2_blocks, 256>>>(ei);
    epilogue_kernel<<<epi_blocks, 256>>>(b1, nullptr, 1);   // -> g_act

    // ---------------- layer 2 ----------------
    zero_kernel<<<zero_blocks, 256>>>();
    sgemm_kernel<<<gemm_grid, 256>>>(nullptr, W2, 1);       // A = g_act
    attn_kernel<<<attn_blocks, 256>>>(as2, ad2);
    edge_softmax_kernel<<<e1_blocks, 256>>>(ei);
    edge_aggregate_kernel<<<e2_blocks, 256>>>(ei);
    epilogue_kernel<<<epi_blocks, 256>>>(b2, out, 0);       // -> d_out
}

// round 2
// speedup vs baseline: 1.3000x; 1.3000x over previous
#include <cuda_runtime.h>
#include <math.h>
#include <stdint.h>

#define N_NODES   50000
#define N_EDGES   800000
#define TOT_EDGES (N_EDGES + N_NODES)
#define HEADS     4
#define OUT_CH    64
#define DHID      256   // HEADS * OUT_CH
#define KDIM      256   // input feature dim for both layers

// ---------------- scratch (static device globals; no allocation) ------------
__device__ float g_h[N_NODES * DHID];       // post-GEMM features [N, H, C]
__device__ float g_act[N_NODES * DHID];     // layer-1 output after ELU
__device__ float g_out[N_NODES * DHID];     // aggregation accumulator
__device__ float g_asrc[N_NODES * HEADS];
__device__ float g_adst[N_NODES * HEADS];
__device__ float g_denom[N_NODES * HEADS];
__device__ float g_eexp[TOT_EDGES * HEADS];

// vector reduction to global (sm_90+)
__device__ __forceinline__ void red_add_v4(float* addr, float4 v) {
    asm volatile("red.global.add.v4.f32 [%0], {%1, %2, %3, %4};"
                 :: "l"(addr), "f"(v.x), "f"(v.y), "f"(v.z), "f"(v.w)
                 : "memory");
}

__device__ __forceinline__ uint32_t f2tf32(float f) {
    uint32_t r;
    asm("cvt.rna.tf32.f32 %0, %1;" : "=r"(r) : "f"(f));
    return r;
}

__device__ __forceinline__ void cp_async16(uint32_t smem_dst, const void* gsrc, int src_bytes) {
    asm volatile("cp.async.cg.shared.global [%0], [%1], 16, %2;"
                 :: "r"(smem_dst), "l"(gsrc), "r"(src_bytes));
}

// ---------------- zero accumulator + denom ----------------------------------
__global__ void zero_kernel() {
    int i = blockIdx.x * blockDim.x + threadIdx.x;
    const int NOUT4 = N_NODES * DHID / 4;    // 3,200,000
    const int NDEN4 = N_NODES * HEADS / 4;   // 50,000
    float4 z = make_float4(0.f, 0.f, 0.f, 0.f);
    if (i < NOUT4) ((float4*)g_out)[i] = z;
    if (i < NDEN4) ((float4*)g_denom)[i] = z;
}

// ---------------- tf32 tensor-core GEMM: g_h = A[M,256] @ B[256,256] --------
// BM=128, BN=128, BK=32; 8 warps in 2x4 grid, warp tile 64x32 (4x4 m16n8k8)
#define BM 128
#define BN 128
#define BK 32
#define AS_STRIDE 36    // (36*r + c) % 32 = (4r + c) % 32 -> conflict-free frag loads
#define BS_STRIDE 136   // (136*k + n) % 32 = (8k + n) % 32 -> conflict-free frag loads

__global__ __launch_bounds__(256) void gemm_tf32_kernel(
    const float* __restrict__ Aext, const float* __restrict__ B, int use_act)
{
    const float* A = use_act ? (const float*)g_act : Aext;
    __shared__ float As[BM][AS_STRIDE];
    __shared__ float Bs[BK][BS_STRIDE];

    int bm = blockIdx.x * BM;
    int bn = blockIdx.y * BN;
    int tid  = threadIdx.x;
    int warp = tid >> 5;
    int lane = tid & 31;
    int wm = (warp & 1) * 64;   // warp row offset within block
    int wn = (warp >> 1) * 32;  // warp col offset within block
    int lr = lane >> 2;         // 0..7
    int lc = lane & 3;          // 0..3

    float c[4][4][4];
    #pragma unroll
    for (int mt = 0; mt < 4; mt++)
        #pragma unroll
        for (int nt = 0; nt < 4; nt++)
            #pragma unroll
            for (int f = 0; f < 4; f++) c[mt][nt][f] = 0.f;

    for (int k0 = 0; k0 < KDIM; k0 += BK) {
        // load A tile [BM x BK]: 4096 floats = 1024 float4
        #pragma unroll
        for (int i = 0; i < 4; i++) {
            int idx = tid + i * 256;
            int r = idx >> 3;           // 0..127
            int cg = (idx & 7) * 4;     // 0..28
            int gr = bm + r;
            int valid = (gr < N_NODES);
            int src_row = valid ? gr : (N_NODES - 1);
            uint32_t dst = (uint32_t)__cvta_generic_to_shared(&As[r][cg]);
            cp_async16(dst, &A[(long)src_row * KDIM + k0 + cg], valid ? 16 : 0);
        }
        // load B tile [BK x BN]: 4096 floats = 1024 float4
        #pragma unroll
        for (int i = 0; i < 4; i++) {
            int idx = tid + i * 256;
            int r = idx >> 5;           // 0..31
            int cg = (idx & 31) * 4;    // 0..124
            uint32_t dst = (uint32_t)__cvta_generic_to_shared(&Bs[r][cg]);
            cp_async16(dst, &B[(long)(k0 + r) * DHID + bn + cg], 16);
        }
        asm volatile("cp.async.commit_group;");
        asm volatile("cp.async.wait_group 0;");
        __syncthreads();

        #pragma unroll
        for (int ks = 0; ks < 4; ks++) {
            int k = ks * 8;
            uint32_t af[4][4];
            #pragma unroll
            for (int mt = 0; mt < 4; mt++) {
                int r0 = wm + mt * 16 + lr;
                af[mt][0] = f2tf32(As[r0][k + lc]);
                af[mt][1] = f2tf32(As[r0 + 8][k + lc]);
                af[mt][2] = f2tf32(As[r0][k + lc + 4]);
                af[mt][3] = f2tf32(As[r0 + 8][k + lc + 4]);
            }
            uint32_t bf[4][2];
            #pragma unroll
            for (int nt = 0; nt < 4; nt++) {
                int col = wn + nt * 8 + lr;
                bf[nt][0] = f2tf32(Bs[k + lc][col]);
                bf[nt][1] = f2tf32(Bs[k + lc + 4][col]);
            }
            #pragma unroll
            for (int mt = 0; mt < 4; mt++)
                #pragma unroll
                for (int nt = 0; nt < 4; nt++) {
                    asm volatile(
                        "mma.sync.aligned.m16n8k8.row.col.f32.tf32.tf32.f32 "
                        "{%0,%1,%2,%3}, {%4,%5,%6,%7}, {%8,%9}, {%0,%1,%2,%3};"
                        : "+f"(c[mt][nt][0]), "+f"(c[mt][nt][1]),
                          "+f"(c[mt][nt][2]), "+f"(c[mt][nt][3])
                        : "r"(af[mt][0]), "r"(af[mt][1]), "r"(af[mt][2]), "r"(af[mt][3]),
                          "r"(bf[nt][0]), "r"(bf[nt][1]));
                }
        }
        __syncthreads();
    }

    // store C
    #pragma unroll
    for (int mt = 0; mt < 4; mt++) {
        int row0 = bm + wm + mt * 16 + lr;
        #pragma unroll
        for (int nt = 0; nt < 4; nt++) {
            int col = bn + wn + nt * 8 + 2 * lc;
            if (row0 < N_NODES)
                *(float2*)&g_h[(long)row0 * DHID + col] =
                    make_float2(c[mt][nt][0], c[mt][nt][1]);
            if (row0 + 8 < N_NODES)
                *(float2*)&g_h[(long)(row0 + 8) * DHID + col] =
                    make_float2(c[mt][nt][2], c[mt][nt][3]);
        }
    }
}

// ---------------- attention scores: a_src/a_dst [N, H] ----------------------
// one warp per (node, head)
__global__ void attn_kernel(const float* __restrict__ att_src,
                            const float* __restrict__ att_dst)
{
    int gw   = (blockIdx.x * blockDim.x + threadIdx.x) >> 5;
    int lane = threadIdx.x & 31;
    if (gw >= N_NODES * HEADS) return;
    int n  = gw >> 2;
    int hd = gw & 3;
    const float* hp = &g_h[(long)n * DHID + hd * OUT_CH];
    const float* as = &att_src[hd * OUT_CH];
    const float* ad = &att_dst[hd * OUT_CH];
    float h0 = hp[lane], h1 = hp[lane + 32];
    float s = h0 * as[lane] + h1 * as[lane + 32];
    float d = h0 * ad[lane] + h1 * ad[lane + 32];
    #pragma unroll
    for (int o = 16; o > 0; o >>= 1) {
        s += __shfl_xor_sync(0xFFFFFFFFu, s, o);
        d += __shfl_xor_sync(0xFFFFFFFFu, d, o);
    }
    if (lane == 0) { g_asrc[gw] = s; g_adst[gw] = d; }
}

// ---------------- edge pass 1: e_exp + denom (softmax w/o max shift) --------
__global__ void edge_softmax_kernel(const int* __restrict__ ei)
{
    int i = blockIdx.x * blockDim.x + threadIdx.x;
    if (i >= TOT_EDGES) return;
    int s, d;
    if (i < N_EDGES) { s = ei[i]; d = ei[N_EDGES + i]; }
    else             { s = d = i - N_EDGES; }   // self loops

    float4 a = *(const float4*)&g_asrc[s * 4];
    float4 b = *(const float4*)&g_adst[d * 4];
    float4 e;
    e.x = a.x + b.x; e.y = a.y + b.y; e.z = a.z + b.z; e.w = a.w + b.w;
    e.x = (e.x > 0.f) ? e.x : 0.2f * e.x;
    e.y = (e.y > 0.f) ? e.y : 0.2f * e.y;
    e.z = (e.z > 0.f) ? e.z : 0.2f * e.z;
    e.w = (e.w > 0.f) ? e.w : 0.2f * e.w;
    e.x = __expf(e.x); e.y = __expf(e.y); e.z = __expf(e.z); e.w = __expf(e.w);

    *(float4*)&g_eexp[(long)i * 4] = e;
    red_add_v4(&g_denom[d * 4], e);
}

// ---------------- edge pass 2: out[dst] += alpha * h[src] -------------------
// one warp per edge; each lane handles 8 contiguous channels (one head each)
__global__ void edge_aggregate_kernel(const int* __restrict__ ei)
{
    int warp = (blockIdx.x * blockDim.x + threadIdx.x) >> 5;
    int lane = threadIdx.x & 31;
    if (warp >= TOT_EDGES) return;
    int s, d;
    if (warp < N_EDGES) { s = ei[warp]; d = ei[N_EDGES + warp]; }
    else                { s = d = warp - N_EDGES; }

    int head = lane >> 3;                     // 8 lanes per head
    float num   = g_eexp[(long)warp * 4 + head];
    float den   = g_denom[d * 4 + head];
    float alpha = num / (den + 1e-16f);

    const float4* hp = (const float4*)&g_h[(long)s * DHID + lane * 8];
    float4 v0 = hp[0];
    float4 v1 = hp[1];
    v0.x *= alpha; v0.y *= alpha; v0.z *= alpha; v0.w *= alpha;
    v1.x *= alpha; v1.y *= alpha; v1.z *= alpha; v1.w *= alpha;

    float* op = &g_out[(long)d * DHID + lane * 8];
    red_add_v4(op, v0);
    red_add_v4(op + 4, v1);
}

// ---------------- epilogue: dst = ELU(out + bias) ---------------------------
__global__ void epilogue_kernel(const float* __restrict__ bias,
                                float* __restrict__ dst_ext, int to_act)
{
    int i = blockIdx.x * blockDim.x + threadIdx.x;
    const int TOT4 = N_NODES * DHID / 4;
    if (i >= TOT4) return;
    float* dst = to_act ? (float*)g_act : dst_ext;
    float4 v = ((const float4*)g_out)[i];
    float4 bz = ((const float4*)bias)[i & 63];   // 64 float4 per row
    v.x += bz.x; v.y += bz.y; v.z += bz.z; v.w += bz.w;
    v.x = (v.x > 0.f) ? v.x : expm1f(v.x);
    v.y = (v.y > 0.f) ? v.y : expm1f(v.y);
    v.z = (v.z > 0.f) ? v.z : expm1f(v.z);
    v.w = (v.w > 0.f) ? v.w : expm1f(v.w);
    ((float4*)dst)[i] = v;
}

// ---------------- launch ----------------------------------------------------
extern "C" void kernel_launch(void* const* d_in, const int* in_sizes, int n_in,
                              void* d_out, int out_size)
{
    const float* x   = (const float*)d_in[0];
    const int*   ei  = (const int*)  d_in[1];
    const float* W1  = (const float*)d_in[2];
    const float* as1 = (const float*)d_in[3];
    const float* ad1 = (const float*)d_in[4];
    const float* b1  = (const float*)d_in[5];
    const float* W2  = (const float*)d_in[6];
    const float* as2 = (const float*)d_in[7];
    const float* ad2 = (const float*)d_in[8];
    const float* b2  = (const float*)d_in[9];
    float* out = (float*)d_out;

    dim3 gemm_grid((N_NODES + BM - 1) / BM, DHID / BN);           // 391 x 2
    int zero_blocks = (N_NODES * DHID / 4 + 255) / 256;           // 12500
    int attn_blocks = (N_NODES * HEADS + 7) / 8;                  // 25000 (8 warps/blk)
    int e1_blocks   = (TOT_EDGES + 255) / 256;                    // 3321
    int e2_blocks   = (TOT_EDGES * 32 + 255) / 256;               // 106250
    int epi_blocks  = zero_blocks;

    // ---------------- layer 1 ----------------
    zero_kernel<<<zero_blocks, 256>>>();
    gemm_tf32_kernel<<<gemm_grid, 256>>>(x, W1, 0);
    attn_kernel<<<attn_blocks, 256>>>(as1, ad1);
    edge_softmax_kernel<<<e1_blocks, 256>>>(ei);
    edge_aggregate_kernel<<<e2_blocks, 256>>>(ei);
    epilogue_kernel<<<epi_blocks, 256>>>(b1, nullptr, 1);   // -> g_act

    // ---------------- layer 2 ----------------
    zero_kernel<<<zero_blocks, 256>>>();
    gemm_tf32_kernel<<<gemm_grid, 256>>>(nullptr, W2, 1);   // A = g_act
    attn_kernel<<<attn_blocks, 256>>>(as2, ad2);
    edge_softmax_kernel<<<e1_blocks, 256>>>(ei);
    edge_aggregate_kernel<<<e2_blocks, 256>>>(ei);
    epilogue_kernel<<<epi_blocks, 256>>>(b2, out, 0);       // -> d_out
}

// round 3
// speedup vs baseline: 2.5536x; 1.9643x over previous
#include <cuda_runtime.h>
#include <math.h>
#include <stdint.h>

#define N_NODES   50000
#define N_EDGES   800000
#define TOT_EDGES (N_EDGES + N_NODES)
#define HEADS     4
#define OUT_CH    64
#define DHID      256
#define KDIM      256
#define NBLK      196        // ceil(N_NODES/256)

// ---------------- scratch (static device globals; no allocation) ------------
__device__ float g_h[N_NODES * DHID];
__device__ float g_act[N_NODES * DHID];
__device__ float g_asrc[N_NODES * HEADS];
__device__ float g_adst[N_NODES * HEADS];
__device__ int   g_deg[N_NODES];
__device__ int   g_rowptr[N_NODES + 1];
__device__ int   g_cursor[N_NODES];
__device__ int   g_csr_src[TOT_EDGES];
__device__ int   g_blocksums[256];

__device__ __forceinline__ uint32_t f2tf32(float f) {
    uint32_t r;
    asm("cvt.rna.tf32.f32 %0, %1;" : "=r"(r) : "f"(f));
    return r;
}

__device__ __forceinline__ void cp_async16(uint32_t smem_dst, const void* gsrc, int src_bytes) {
    asm volatile("cp.async.cg.shared.global [%0], [%1], 16, %2;"
                 :: "r"(smem_dst), "l"(gsrc), "r"(src_bytes));
}

// ========================= CSR build =========================
__global__ void zero_deg_kernel() {
    int i = blockIdx.x * blockDim.x + threadIdx.x;
    if (i < N_NODES) g_deg[i] = 0;
}

__global__ void count_kernel(const int* __restrict__ ei) {
    int i = blockIdx.x * blockDim.x + threadIdx.x;
    if (i >= TOT_EDGES) return;
    int d = (i < N_EDGES) ? ei[N_EDGES + i] : (i - N_EDGES);
    atomicAdd(&g_deg[d], 1);
}

// per-block (256 nodes) sum of degrees -> g_blocksums[b]
__global__ void block_reduce_kernel() {
    __shared__ int sh[256];
    int t = threadIdx.x;
    int i = blockIdx.x * 256 + t;
    sh[t] = (i < N_NODES) ? g_deg[i] : 0;
    __syncthreads();
    for (int o = 128; o > 0; o >>= 1) {
        if (t < o) sh[t] += sh[t + o];
        __syncthreads();
    }
    if (t == 0) g_blocksums[blockIdx.x] = sh[0];
}

// single block: exclusive scan over NBLK block sums
__global__ void scan_blocks_kernel() {
    __shared__ int sh[256];
    int t = threadIdx.x;
    int v = (t < NBLK) ? g_blocksums[t] : 0;
    sh[t] = v;
    __syncthreads();
    for (int o = 1; o < 256; o <<= 1) {
        int x = (t >= o) ? sh[t - o] : 0;
        __syncthreads();
        sh[t] += x;
        __syncthreads();
    }
    if (t < NBLK) g_blocksums[t] = sh[t] - v;   // exclusive
}

// per-block exclusive scan + offset -> rowptr, cursor
__global__ void scatter_rowptr_kernel() {
    __shared__ int sh[256];
    int t = threadIdx.x;
    int i = blockIdx.x * 256 + t;
    int v = (i < N_NODES) ? g_deg[i] : 0;
    sh[t] = v;
    __syncthreads();
    for (int o = 1; o < 256; o <<= 1) {
        int x = (t >= o) ? sh[t - o] : 0;
        __syncthreads();
        sh[t] += x;
        __syncthreads();
    }
    int off = g_blocksums[blockIdx.x];
    if (i < N_NODES) {
        int r = off + sh[t] - v;      // exclusive
        g_rowptr[i] = r;
        g_cursor[i] = r;
        if (i == N_NODES - 1) g_rowptr[N_NODES] = TOT_EDGES;
    }
}

__global__ void fill_kernel(const int* __restrict__ ei) {
    int i = blockIdx.x * blockDim.x + threadIdx.x;
    if (i >= TOT_EDGES) return;
    int s, d;
    if (i < N_EDGES) { s = ei[i]; d = ei[N_EDGES + i]; }
    else             { s = d = i - N_EDGES; }
    int pos = atomicAdd(&g_cursor[d], 1);
    g_csr_src[pos] = s;
}

// ========================= tf32 tensor-core GEMM =========================
// BM=128, BN=128, BK=32; 8 warps (2x4), warp tile 64x32 (4x4 m16n8k8)
#define BM 128
#define BN 128
#define BK 32
#define AS_STRIDE 36
#define BS_STRIDE 136

__global__ __launch_bounds__(256) void gemm_tf32_kernel(
    const float* __restrict__ Aext, const float* __restrict__ B, int use_act)
{
    const float* A = use_act ? (const float*)g_act : Aext;
    __shared__ float As[BM][AS_STRIDE];
    __shared__ float Bs[BK][BS_STRIDE];

    int bm = blockIdx.x * BM;
    int bn = blockIdx.y * BN;
    int tid  = threadIdx.x;
    int warp = tid >> 5;
    int lane = tid & 31;
    int wm = (warp & 1) * 64;
    int wn = (warp >> 1) * 32;
    int lr = lane >> 2;
    int lc = lane & 3;

    float c[4][4][4];
    #pragma unroll
    for (int mt = 0; mt < 4; mt++)
        #pragma unroll
        for (int nt = 0; nt < 4; nt++)
            #pragma unroll
            for (int f = 0; f < 4; f++) c[mt][nt][f] = 0.f;

    for (int k0 = 0; k0 < KDIM; k0 += BK) {
        #pragma unroll
        for (int i = 0; i < 4; i++) {
            int idx = tid + i * 256;
            int r = idx >> 3;
            int cg = (idx & 7) * 4;
            int gr = bm + r;
            int valid = (gr < N_NODES);
            int src_row = valid ? gr : (N_NODES - 1);
            uint32_t dst = (uint32_t)__cvta_generic_to_shared(&As[r][cg]);
            cp_async16(dst, &A[(long)src_row * KDIM + k0 + cg], valid ? 16 : 0);
        }
        #pragma unroll
        for (int i = 0; i < 4; i++) {
            int idx = tid + i * 256;
            int r = idx >> 5;
            int cg = (idx & 31) * 4;
            uint32_t dst = (uint32_t)__cvta_generic_to_shared(&Bs[r][cg]);
            cp_async16(dst, &B[(long)(k0 + r) * DHID + bn + cg], 16);
        }
        asm volatile("cp.async.commit_group;");
        asm volatile("cp.async.wait_group 0;");
        __syncthreads();

        #pragma unroll
        for (int ks = 0; ks < 4; ks++) {
            int k = ks * 8;
            uint32_t af[4][4];
            #pragma unroll
            for (int mt = 0; mt < 4; mt++) {
                int r0 = wm + mt * 16 + lr;
                af[mt][0] = f2tf32(As[r0][k + lc]);
                af[mt][1] = f2tf32(As[r0 + 8][k + lc]);
                af[mt][2] = f2tf32(As[r0][k + lc + 4]);
                af[mt][3] = f2tf32(As[r0 + 8][k + lc + 4]);
            }
            uint32_t bf[4][2];
            #pragma unroll
            for (int nt = 0; nt < 4; nt++) {
                int col = wn + nt * 8 + lr;
                bf[nt][0] = f2tf32(Bs[k + lc][col]);
                bf[nt][1] = f2tf32(Bs[k + lc + 4][col]);
            }
            #pragma unroll
            for (int mt = 0; mt < 4; mt++)
                #pragma unroll
                for (int nt = 0; nt < 4; nt++) {
                    asm volatile(
                        "mma.sync.aligned.m16n8k8.row.col.f32.tf32.tf32.f32 "
                        "{%0,%1,%2,%3}, {%4,%5,%6,%7}, {%8,%9}, {%0,%1,%2,%3};"
                        : "+f"(c[mt][nt][0]), "+f"(c[mt][nt][1]),
                          "+f"(c[mt][nt][2]), "+f"(c[mt][nt][3])
                        : "r"(af[mt][0]), "r"(af[mt][1]), "r"(af[mt][2]), "r"(af[mt][3]),
                          "r"(bf[nt][0]), "r"(bf[nt][1]));
                }
        }
        __syncthreads();
    }

    #pragma unroll
    for (int mt = 0; mt < 4; mt++) {
        int row0 = bm + wm + mt * 16 + lr;
        #pragma unroll
        for (int nt = 0; nt < 4; nt++) {
            int col = bn + wn + nt * 8 + 2 * lc;
            if (row0 < N_NODES)
                *(float2*)&g_h[(long)row0 * DHID + col] =
                    make_float2(c[mt][nt][0], c[mt][nt][1]);
            if (row0 + 8 < N_NODES)
                *(float2*)&g_h[(long)(row0 + 8) * DHID + col] =
                    make_float2(c[mt][nt][2], c[mt][nt][3]);
        }
    }
}

// ========================= attention scores =========================
__global__ void attn_kernel(const float* __restrict__ att_src,
                            const float* __restrict__ att_dst)
{
    int gw   = (blockIdx.x * blockDim.x + threadIdx.x) >> 5;
    int lane = threadIdx.x & 31;
    if (gw >= N_NODES * HEADS) return;
    int n  = gw >> 2;
    int hd = gw & 3;
    const float* hp = &g_h[(long)n * DHID + hd * OUT_CH];
    const float* as = &att_src[hd * OUT_CH];
    const float* ad = &att_dst[hd * OUT_CH];
    float h0 = hp[lane], h1 = hp[lane + 32];
    float s = h0 * as[lane] + h1 * as[lane + 32];
    float d = h0 * ad[lane] + h1 * ad[lane + 32];
    #pragma unroll
    for (int o = 16; o > 0; o >>= 1) {
        s += __shfl_xor_sync(0xFFFFFFFFu, s, o);
        d += __shfl_xor_sync(0xFFFFFFFFu, d, o);
    }
    if (lane == 0) { g_asrc[gw] = s; g_adst[gw] = d; }
}

// ========================= fused aggregate (warp per node) =========================
// pass 1: softmax denominator; pass 2: register-accumulate alpha*h[src];
// epilogue: +bias, ELU, single coalesced row store.
__device__ __forceinline__ float4 eexp4(float4 a, float4 b) {
    float4 e;
    e.x = a.x + b.x; e.y = a.y + b.y; e.z = a.z + b.z; e.w = a.w + b.w;
    e.x = (e.x > 0.f) ? e.x : 0.2f * e.x;
    e.y = (e.y > 0.f) ? e.y : 0.2f * e.y;
    e.z = (e.z > 0.f) ? e.z : 0.2f * e.z;
    e.w = (e.w > 0.f) ? e.w : 0.2f * e.w;
    e.x = __expf(e.x); e.y = __expf(e.y); e.z = __expf(e.z); e.w = __expf(e.w);
    return e;
}

__global__ __launch_bounds__(256) void gat_aggregate_kernel(
    const float* __restrict__ bias, float* __restrict__ dst_ext, int to_act)
{
    int n    = (blockIdx.x * blockDim.x + threadIdx.x) >> 5;
    int lane = threadIdx.x & 31;
    if (n >= N_NODES) return;
    int beg = g_rowptr[n];
    int end = g_rowptr[n + 1];
    float4 adst = *(const float4*)&g_adst[n * 4];

    // pass 1: denominator
    float4 dsum = make_float4(0.f, 0.f, 0.f, 0.f);
    for (int e = beg + lane; e < end; e += 32) {
        int s = g_csr_src[e];
        float4 a = *(const float4*)&g_asrc[s * 4];
        float4 ee = eexp4(a, adst);
        dsum.x += ee.x; dsum.y += ee.y; dsum.z += ee.z; dsum.w += ee.w;
    }
    #pragma unroll
    for (int o = 16; o > 0; o >>= 1) {
        dsum.x += __shfl_xor_sync(0xFFFFFFFFu, dsum.x, o);
        dsum.y += __shfl_xor_sync(0xFFFFFFFFu, dsum.y, o);
        dsum.z += __shfl_xor_sync(0xFFFFFFFFu, dsum.z, o);
        dsum.w += __shfl_xor_sync(0xFFFFFFFFu, dsum.w, o);
    }
    int head = lane >> 3;   // lane covers channels [lane*8, lane*8+8) -> head = lane/8
    float den = (head == 0) ? dsum.x : (head == 1) ? dsum.y : (head == 2) ? dsum.z : dsum.w;
    float inv = 1.f / (den + 1e-16f);

    // pass 2: accumulate alpha * h[src]
    float4 acc0 = make_float4(0.f, 0.f, 0.f, 0.f);
    float4 acc1 = make_float4(0.f, 0.f, 0.f, 0.f);
    int s_cur = (beg < end) ? g_csr_src[beg] : 0;
    for (int e = beg; e < end; e++) {
        int s_next = (e + 1 < end) ? g_csr_src[e + 1] : 0;
        float4 a = *(const float4*)&g_asrc[s_cur * 4];
        float4 ee = eexp4(a, adst);
        float eh = (head == 0) ? ee.x : (head == 1) ? ee.y : (head == 2) ? ee.z : ee.w;
        float alpha = eh * inv;
        const float4* hp = (const float4*)&g_h[(long)s_cur * DHID + lane * 8];
        float4 v0 = hp[0];
        float4 v1 = hp[1];
        acc0.x += alpha * v0.x; acc0.y += alpha * v0.y;
        acc0.z += alpha * v0.z; acc0.w += alpha * v0.w;
        acc1.x += alpha * v1.x; acc1.y += alpha * v1.y;
        acc1.z += alpha * v1.z; acc1.w += alpha * v1.w;
        s_cur = s_next;
    }

    // epilogue: bias + ELU + store
    float4 b0 = ((const float4*)bias)[lane * 2];
    float4 b1 = ((const float4*)bias)[lane * 2 + 1];
    acc0.x += b0.x; acc0.y += b0.y; acc0.z += b0.z; acc0.w += b0.w;
    acc1.x += b1.x; acc1.y += b1.y; acc1.z += b1.z; acc1.w += b1.w;
    acc0.x = (acc0.x > 0.f) ? acc0.x : expm1f(acc0.x);
    acc0.y = (acc0.y > 0.f) ? acc0.y : expm1f(acc0.y);
    acc0.z = (acc0.z > 0.f) ? acc0.z : expm1f(acc0.z);
    acc0.w = (acc0.w > 0.f) ? acc0.w : expm1f(acc0.w);
    acc1.x = (acc1.x > 0.f) ? acc1.x : expm1f(acc1.x);
    acc1.y = (acc1.y > 0.f) ? acc1.y : expm1f(acc1.y);
    acc1.z = (acc1.z > 0.f) ? acc1.z : expm1f(acc1.z);
    acc1.w = (acc1.w > 0.f) ? acc1.w : expm1f(acc1.w);

    float* dst = to_act ? (float*)g_act : dst_ext;
    float* op = &dst[(long)n * DHID + lane * 8];
    *(float4*)op = acc0;
    *(float4*)(op + 4) = acc1;
}

// ========================= launch =========================
extern "C" void kernel_launch(void* const* d_in, const int* in_sizes, int n_in,
                              void* d_out, int out_size)
{
    const float* x   = (const float*)d_in[0];
    const int*   ei  = (const int*)  d_in[1];
    const float* W1  = (const float*)d_in[2];
    const float* as1 = (const float*)d_in[3];
    const float* ad1 = (const float*)d_in[4];
    const float* b1  = (const float*)d_in[5];
    const float* W2  = (const float*)d_in[6];
    const float* as2 = (const float*)d_in[7];
    const float* ad2 = (const float*)d_in[8];
    const float* b2  = (const float*)d_in[9];
    float* out = (float*)d_out;

    dim3 gemm_grid((N_NODES + BM - 1) / BM, DHID / BN);
    int edge_blocks = (TOT_EDGES + 255) / 256;
    int attn_blocks = (N_NODES * HEADS + 7) / 8;
    int agg_blocks  = (N_NODES + 7) / 8;          // 8 warps per block

    // ---- CSR build (layer-independent, rebuilt each replay) ----
    zero_deg_kernel<<<NBLK, 256>>>();
    count_kernel<<<edge_blocks, 256>>>(ei);
    block_reduce_kernel<<<NBLK, 256>>>();
    scan_blocks_kernel<<<1, 256>>>();
    scatter_rowptr_kernel<<<NBLK, 256>>>();
    fill_kernel<<<edge_blocks, 256>>>(ei);

    // ---- layer 1 ----
    gemm_tf32_kernel<<<gemm_grid, 256>>>(x, W1, 0);
    attn_kernel<<<attn_blocks, 256>>>(as1, ad1);
    gat_aggregate_kernel<<<agg_blocks, 256>>>(b1, nullptr, 1);

    // ---- layer 2 ----
    gemm_tf32_kernel<<<gemm_grid, 256>>>(nullptr, W2, 1);
    attn_kernel<<<attn_blocks, 256>>>(as2, ad2);
    gat_aggregate_kernel<<<agg_blocks, 256>>>(b2, out, 0);
}

// round 4
// speedup vs baseline: 2.9272x; 1.1463x over previous
#include <cuda_runtime.h>
#include <cuda_fp16.h>
#include <math.h>
#include <stdint.h>

#define N_NODES   50000
#define N_EDGES   800000
#define TOT_EDGES (N_EDGES + N_NODES)
#define HEADS     4
#define OUT_CH    64
#define DHID      256
#define KDIM      256
#define NBLK      196        // ceil(N_NODES/256)

// ---------------- scratch (static device globals; no allocation) ------------
__device__ __half g_h_half[N_NODES * DHID];   // fp16 features for gather
__device__ float  g_act[N_NODES * DHID];      // layer-1 output after ELU
__device__ float  g_asrc[N_NODES * HEADS];
__device__ float  g_adst[N_NODES * HEADS];
__device__ int    g_deg[N_NODES];
__device__ int    g_rowptr[N_NODES + 1];
__device__ int    g_cursor[N_NODES];
__device__ int    g_csr_src[TOT_EDGES];
__device__ int    g_blocksums[256];

__device__ __forceinline__ uint32_t f2tf32(float f) {
    uint32_t r;
    asm("cvt.rna.tf32.f32 %0, %1;" : "=r"(r) : "f"(f));
    return r;
}

__device__ __forceinline__ void cp_async16(uint32_t smem_dst, const void* gsrc, int src_bytes) {
    asm volatile("cp.async.cg.shared.global [%0], [%1], 16, %2;"
                 :: "r"(smem_dst), "l"(gsrc), "r"(src_bytes));
}

// ========================= CSR build =========================
__global__ void zero_deg_kernel() {
    int i = blockIdx.x * blockDim.x + threadIdx.x;
    if (i < N_NODES) g_deg[i] = 0;
}

__global__ void count_kernel(const int* __restrict__ ei) {
    int i = blockIdx.x * blockDim.x + threadIdx.x;
    if (i >= TOT_EDGES) return;
    int d = (i < N_EDGES) ? ei[N_EDGES + i] : (i - N_EDGES);
    atomicAdd(&g_deg[d], 1);
}

__global__ void block_reduce_kernel() {
    __shared__ int sh[256];
    int t = threadIdx.x;
    int i = blockIdx.x * 256 + t;
    sh[t] = (i < N_NODES) ? g_deg[i] : 0;
    __syncthreads();
    for (int o = 128; o > 0; o >>= 1) {
        if (t < o) sh[t] += sh[t + o];
        __syncthreads();
    }
    if (t == 0) g_blocksums[blockIdx.x] = sh[0];
}

__global__ void scan_blocks_kernel() {
    __shared__ int sh[256];
    int t = threadIdx.x;
    int v = (t < NBLK) ? g_blocksums[t] : 0;
    sh[t] = v;
    __syncthreads();
    for (int o = 1; o < 256; o <<= 1) {
        int x = (t >= o) ? sh[t - o] : 0;
        __syncthreads();
        sh[t] += x;
        __syncthreads();
    }
    if (t < NBLK) g_blocksums[t] = sh[t] - v;
}

__global__ void scatter_rowptr_kernel() {
    __shared__ int sh[256];
    int t = threadIdx.x;
    int i = blockIdx.x * 256 + t;
    int v = (i < N_NODES) ? g_deg[i] : 0;
    sh[t] = v;
    __syncthreads();
    for (int o = 1; o < 256; o <<= 1) {
        int x = (t >= o) ? sh[t - o] : 0;
        __syncthreads();
        sh[t] += x;
        __syncthreads();
    }
    int off = g_blocksums[blockIdx.x];
    if (i < N_NODES) {
        int r = off + sh[t] - v;
        g_rowptr[i] = r;
        g_cursor[i] = r;
        if (i == N_NODES - 1) g_rowptr[N_NODES] = TOT_EDGES;
    }
}

__global__ void fill_kernel(const int* __restrict__ ei) {
    int i = blockIdx.x * blockDim.x + threadIdx.x;
    if (i >= TOT_EDGES) return;
    int s, d;
    if (i < N_EDGES) { s = ei[i]; d = ei[N_EDGES + i]; }
    else             { s = d = i - N_EDGES; }
    int pos = atomicAdd(&g_cursor[d], 1);
    g_csr_src[pos] = s;
}

// ========================= tf32 GEMM + fused attn scores + fp16 store ========
// BM=128, BN=128, BK=32; 8 warps (2x4), warp tile 64x32 (4x4 m16n8k8)
// double-buffered cp.async. Epilogue computes a_src/a_dst from fp32 accs
// (block covers heads 2*by, 2*by+1 exclusively) and stores h as fp16.
#define BM 128
#define BN 128
#define BK 32
#define AS_STRIDE 36
#define BS_STRIDE 136

__global__ __launch_bounds__(256) void gemm_tf32_kernel(
    const float* __restrict__ Aext, const float* __restrict__ B,
    const float* __restrict__ att_src, const float* __restrict__ att_dst,
    int use_act)
{
    const float* A = use_act ? (const float*)g_act : Aext;
    __shared__ float As[2][BM][AS_STRIDE];
    __shared__ float Bs[2][BK][BS_STRIDE];
    __shared__ float s_attn[2][2][2][BM];  // [src/dst][head_local][slot][row]

    int bm = blockIdx.x * BM;
    int bn = blockIdx.y * BN;
    int tid  = threadIdx.x;
    int warp = tid >> 5;
    int lane = tid & 31;
    int wm = (warp & 1) * 64;
    int wn = (warp >> 1) * 32;
    int lr = lane >> 2;
    int lc = lane & 3;

    float c[4][4][4];
    #pragma unroll
    for (int mt = 0; mt < 4; mt++)
        #pragma unroll
        for (int nt = 0; nt < 4; nt++)
            #pragma unroll
            for (int f = 0; f < 4; f++) c[mt][nt][f] = 0.f;

    // ---- tile loader (stage st, k-offset k0) ----
    auto load_tiles = [&](int st, int k0) {
        #pragma unroll
        for (int i = 0; i < 4; i++) {
            int idx = tid + i * 256;
            int r = idx >> 3;
            int cg = (idx & 7) * 4;
            int gr = bm + r;
            int valid = (gr < N_NODES);
            int src_row = valid ? gr : 0;
            uint32_t dst = (uint32_t)__cvta_generic_to_shared(&As[st][r][cg]);
            cp_async16(dst, &A[(long)src_row * KDIM + k0 + cg], valid ? 16 : 0);
        }
        #pragma unroll
        for (int i = 0; i < 4; i++) {
            int idx = tid + i * 256;
            int r = idx >> 5;
            int cg = (idx & 31) * 4;
            uint32_t dst = (uint32_t)__cvta_generic_to_shared(&Bs[st][r][cg]);
            cp_async16(dst, &B[(long)(k0 + r) * DHID + bn + cg], 16);
        }
        asm volatile("cp.async.commit_group;");
    };

    load_tiles(0, 0);

    const int NITER = KDIM / BK;   // 8
    #pragma unroll 1
    for (int it = 0; it < NITER; it++) {
        if (it + 1 < NITER) load_tiles((it + 1) & 1, (it + 1) * BK);
        if (it + 1 < NITER) asm volatile("cp.async.wait_group 1;");
        else                asm volatile("cp.async.wait_group 0;");
        __syncthreads();
        int st = it & 1;

        #pragma unroll
        for (int ks = 0; ks < 4; ks++) {
            int k = ks * 8;
            uint32_t af[4][4];
            #pragma unroll
            for (int mt = 0; mt < 4; mt++) {
                int r0 = wm + mt * 16 + lr;
                af[mt][0] = f2tf32(As[st][r0][k + lc]);
                af[mt][1] = f2tf32(As[st][r0 + 8][k + lc]);
                af[mt][2] = f2tf32(As[st][r0][k + lc + 4]);
                af[mt][3] = f2tf32(As[st][r0 + 8][k + lc + 4]);
            }
            uint32_t bf[4][2];
            #pragma unroll
            for (int nt = 0; nt < 4; nt++) {
                int col = wn + nt * 8 + lr;
                bf[nt][0] = f2tf32(Bs[st][k + lc][col]);
                bf[nt][1] = f2tf32(Bs[st][k + lc + 4][col]);
            }
            #pragma unroll
            for (int mt = 0; mt < 4; mt++)
                #pragma unroll
                for (int nt = 0; nt < 4; nt++) {
                    asm volatile(
                        "mma.sync.aligned.m16n8k8.row.col.f32.tf32.tf32.f32 "
                        "{%0,%1,%2,%3}, {%4,%5,%6,%7}, {%8,%9}, {%0,%1,%2,%3};"
                        : "+f"(c[mt][nt][0]), "+f"(c[mt][nt][1]),
                          "+f"(c[mt][nt][2]), "+f"(c[mt][nt][3])
                        : "r"(af[mt][0]), "r"(af[mt][1]), "r"(af[mt][2]), "r"(af[mt][3]),
                          "r"(bf[nt][0]), "r"(bf[nt][1]));
                }
        }
        __syncthreads();
    }

    // ---- store C as fp16 ----
    #pragma unroll
    for (int mt = 0; mt < 4; mt++) {
        int row0 = bm + wm + mt * 16 + lr;
        #pragma unroll
        for (int nt = 0; nt < 4; nt++) {
            int col = bn + wn + nt * 8 + 2 * lc;
            if (row0 < N_NODES)
                *(__half2*)&g_h_half[(long)row0 * DHID + col] =
                    __floats2half2_rn(c[mt][nt][0], c[mt][nt][1]);
            if (row0 + 8 < N_NODES)
                *(__half2*)&g_h_half[(long)(row0 + 8) * DHID + col] =
                    __floats2half2_rn(c[mt][nt][2], c[mt][nt][3]);
        }
    }

    // ---- fused attention scores ----
    // warp's 32 cols lie in one local head: head_l = wn>>6; slot = (wn>>5)&1
    int head_l = wn >> 6;
    int slot   = (wn >> 5) & 1;
    float attS[4][2], attD[4][2];
    #pragma unroll
    for (int nt = 0; nt < 4; nt++)
        #pragma unroll
        for (int j = 0; j < 2; j++) {
            int col = bn + wn + nt * 8 + 2 * lc + j;
            attS[nt][j] = att_src[col];
            attD[nt][j] = att_dst[col];
        }
    #pragma unroll
    for (int mt = 0; mt < 4; mt++) {
        float s0 = 0.f, d0 = 0.f, s1 = 0.f, d1 = 0.f;
        #pragma unroll
        for (int nt = 0; nt < 4; nt++) {
            s0 += c[mt][nt][0] * attS[nt][0] + c[mt][nt][1] * attS[nt][1];
            d0 += c[mt][nt][0] * attD[nt][0] + c[mt][nt][1] * attD[nt][1];
            s1 += c[mt][nt][2] * attS[nt][0] + c[mt][nt][3] * attS[nt][1];
            d1 += c[mt][nt][2] * attD[nt][0] + c[mt][nt][3] * attD[nt][1];
        }
        // reduce over the 4 lanes sharing this row (lc = 0..3)
        #pragma unroll
        for (int o = 1; o < 4; o <<= 1) {
            s0 += __shfl_xor_sync(0xFFFFFFFFu, s0, o);
            d0 += __shfl_xor_sync(0xFFFFFFFFu, d0, o);
            s1 += __shfl_xor_sync(0xFFFFFFFFu, s1, o);
            d1 += __shfl_xor_sync(0xFFFFFFFFu, d1, o);
        }
        if (lc == 0) {
            int r0 = wm + mt * 16 + lr;
            s_attn[0][head_l][slot][r0]     = s0;
            s_attn[1][head_l][slot][r0]     = d0;
            s_attn[0][head_l][slot][r0 + 8] = s1;
            s_attn[1][head_l][slot][r0 + 8] = d1;
        }
    }
    __syncthreads();
    // 256 threads: each handles one (row, head_local) pair
    {
        int row = tid & 127;
        int hl  = tid >> 7;
        int node = bm + row;
        if (node < N_NODES) {
            int hg = blockIdx.y * 2 + hl;
            g_asrc[node * 4 + hg] = s_attn[0][hl][0][row] + s_attn[0][hl][1][row];
            g_adst[node * 4 + hg] = s_attn[1][hl][0][row] + s_attn[1][hl][1][row];
        }
    }
}

// ========================= fused aggregate (warp per node) ====================
__device__ __forceinline__ float4 eexp4(float4 a, float4 b) {
    float4 e;
    e.x = a.x + b.x; e.y = a.y + b.y; e.z = a.z + b.z; e.w = a.w + b.w;
    e.x = (e.x > 0.f) ? e.x : 0.2f * e.x;
    e.y = (e.y > 0.f) ? e.y : 0.2f * e.y;
    e.z = (e.z > 0.f) ? e.z : 0.2f * e.z;
    e.w = (e.w > 0.f) ? e.w : 0.2f * e.w;
    e.x = __expf(e.x); e.y = __expf(e.y); e.z = __expf(e.z); e.w = __expf(e.w);
    return e;
}

__global__ __launch_bounds__(256) void gat_aggregate_kernel(
    const float* __restrict__ bias, float* __restrict__ dst_ext, int to_act)
{
    int n    = (blockIdx.x * blockDim.x + threadIdx.x) >> 5;
    int lane = threadIdx.x & 31;
    if (n >= N_NODES) return;
    int beg = g_rowptr[n];
    int end = g_rowptr[n + 1];
    float4 adst = *(const float4*)&g_adst[n * 4];

    // pass 1: denominator
    float4 dsum = make_float4(0.f, 0.f, 0.f, 0.f);
    for (int e = beg + lane; e < end; e += 32) {
        int s = g_csr_src[e];
        float4 a = *(const float4*)&g_asrc[s * 4];
        float4 ee = eexp4(a, adst);
        dsum.x += ee.x; dsum.y += ee.y; dsum.z += ee.z; dsum.w += ee.w;
    }
    #pragma unroll
    for (int o = 16; o > 0; o >>= 1) {
        dsum.x += __shfl_xor_sync(0xFFFFFFFFu, dsum.x, o);
        dsum.y += __shfl_xor_sync(0xFFFFFFFFu, dsum.y, o);
        dsum.z += __shfl_xor_sync(0xFFFFFFFFu, dsum.z, o);
        dsum.w += __shfl_xor_sync(0xFFFFFFFFu, dsum.w, o);
    }
    int head = lane >> 3;
    float den = (head == 0) ? dsum.x : (head == 1) ? dsum.y : (head == 2) ? dsum.z : dsum.w;
    float inv = 1.f / (den + 1e-16f);

    // pass 2: accumulate alpha * h[src] (fp16 gather, fp32 accumulate)
    float acc[8] = {0.f, 0.f, 0.f, 0.f, 0.f, 0.f, 0.f, 0.f};
    int s_cur = (beg < end) ? g_csr_src[beg] : 0;
    for (int e = beg; e < end; e++) {
        int s_next = (e + 1 < end) ? g_csr_src[e + 1] : 0;
        float4 a = *(const float4*)&g_asrc[s_cur * 4];
        float4 ee = eexp4(a, adst);
        float eh = (head == 0) ? ee.x : (head == 1) ? ee.y : (head == 2) ? ee.z : ee.w;
        float alpha = eh * inv;
        uint4 raw = *(const uint4*)&g_h_half[(long)s_cur * DHID + lane * 8];
        float2 f0 = __half22float2(*(__half2*)&raw.x);
        float2 f1 = __half22float2(*(__half2*)&raw.y);
        float2 f2 = __half22float2(*(__half2*)&raw.z);
        float2 f3 = __half22float2(*(__half2*)&raw.w);
        acc[0] += alpha * f0.x; acc[1] += alpha * f0.y;
        acc[2] += alpha * f1.x; acc[3] += alpha * f1.y;
        acc[4] += alpha * f2.x; acc[5] += alpha * f2.y;
        acc[6] += alpha * f3.x; acc[7] += alpha * f3.y;
        s_cur = s_next;
    }

    // epilogue: bias + ELU + store
    float4 b0 = ((const float4*)bias)[lane * 2];
    float4 b1 = ((const float4*)bias)[lane * 2 + 1];
    float bb[8] = {b0.x, b0.y, b0.z, b0.w, b1.x, b1.y, b1.z, b1.w};
    #pragma unroll
    for (int i = 0; i < 8; i++) {
        float v = acc[i] + bb[i];
        acc[i] = (v > 0.f) ? v : expm1f(v);
    }
    float* dst = to_act ? (float*)g_act : dst_ext;
    float* op = &dst[(long)n * DHID + lane * 8];
    *(float4*)op       = make_float4(acc[0], acc[1], acc[2], acc[3]);
    *(float4*)(op + 4) = make_float4(acc[4], acc[5], acc[6], acc[7]);
}

// ========================= launch =========================
extern "C" void kernel_launch(void* const* d_in, const int* in_sizes, int n_in,
                              void* d_out, int out_size)
{
    const float* x   = (const float*)d_in[0];
    const int*   ei  = (const int*)  d_in[1];
    const float* W1  = (const float*)d_in[2];
    const float* as1 = (const float*)d_in[3];
    const float* ad1 = (const float*)d_in[4];
    const float* b1  = (const float*)d_in[5];
    const float* W2  = (const float*)d_in[6];
    const float* as2 = (const float*)d_in[7];
    const float* ad2 = (const float*)d_in[8];
    const float* b2  = (const float*)d_in[9];
    float* out = (float*)d_out;

    dim3 gemm_grid((N_NODES + BM - 1) / BM, DHID / BN);
    int edge_blocks = (TOT_EDGES + 255) / 256;
    int agg_blocks  = (N_NODES + 7) / 8;

    // ---- CSR build ----
    zero_deg_kernel<<<NBLK, 256>>>();
    count_kernel<<<edge_blocks, 256>>>(ei);
    block_reduce_kernel<<<NBLK, 256>>>();
    scan_blocks_kernel<<<1, 256>>>();
    scatter_rowptr_kernel<<<NBLK, 256>>>();
    fill_kernel<<<edge_blocks, 256>>>(ei);

    // ---- layer 1 ----
    gemm_tf32_kernel<<<gemm_grid, 256>>>(x, W1, as1, ad1, 0);
    gat_aggregate_kernel<<<agg_blocks, 256>>>(b1, nullptr, 1);

    // ---- layer 2 ----
    gemm_tf32_kernel<<<gemm_grid, 256>>>(nullptr, W2, as2, ad2, 1);
    gat_aggregate_kernel<<<agg_blocks, 256>>>(b2, out, 0);
}

// round 6
// speedup vs baseline: 3.9322x; 1.3433x over previous
#include <cuda_runtime.h>
#include <cuda_fp16.h>
#include <math.h>
#include <stdint.h>

#define N_NODES   50000
#define N_EDGES   800000
#define TOT_EDGES (N_EDGES + N_NODES)
#define HEADS     4
#define OUT_CH    64
#define DHID      256
#define KDIM      256
#define NBLK      196        // ceil(N_NODES/256)

// ---------------- scratch (static device globals; no allocation) ------------
__device__ __half g_h_half[N_NODES * DHID];   // fp16 features for gather
__device__ __half g_act[N_NODES * DHID];      // layer-1 output after ELU (half)
__device__ __half g_x_half[N_NODES * KDIM];   // fp16 copy of input x
__device__ __half g_w1t[DHID * KDIM];         // W1^T in half: [n][k]
__device__ __half g_w2t[DHID * KDIM];         // W2^T in half
__device__ float  g_asrc[N_NODES * HEADS];
__device__ float  g_adst[N_NODES * HEADS];
__device__ int    g_deg[N_NODES];
__device__ int    g_rowptr[N_NODES + 1];
__device__ int    g_cursor[N_NODES];
__device__ int    g_csr_src[TOT_EDGES];
__device__ int    g_blocksums[256];

__device__ __forceinline__ void cp_async16(uint32_t smem_dst, const void* gsrc, int src_bytes) {
    asm volatile("cp.async.cg.shared.global [%0], [%1], 16, %2;"
                 :: "r"(smem_dst), "l"(gsrc), "r"(src_bytes));
}

// ========================= input conversion =========================
__global__ void convert_x_kernel(const float* __restrict__ x) {
    int i = blockIdx.x * blockDim.x + threadIdx.x;
    const int TOT8 = N_NODES * KDIM / 8;
    if (i >= TOT8) return;
    float4 v0 = ((const float4*)x)[2 * i];
    float4 v1 = ((const float4*)x)[2 * i + 1];
    __half2 h0 = __floats2half2_rn(v0.x, v0.y);
    __half2 h1 = __floats2half2_rn(v0.z, v0.w);
    __half2 h2 = __floats2half2_rn(v1.x, v1.y);
    __half2 h3 = __floats2half2_rn(v1.z, v1.w);
    uint4 packed = make_uint4(*(uint32_t*)&h0, *(uint32_t*)&h1,
                              *(uint32_t*)&h2, *(uint32_t*)&h3);
    ((uint4*)g_x_half)[i] = packed;
}

// transpose + convert W [K][N] fp32 -> Wt [N][K] half  (32x32 smem tiles)
// which: 0 -> g_w1t, 1 -> g_w2t  (device symbols must be resolved device-side)
__global__ void convert_w_kernel(const float* __restrict__ W, int which) {
    __half* Wt = which ? g_w2t : g_w1t;
    __shared__ float tile[32][33];
    int bx = blockIdx.x * 32, by = blockIdx.y * 32;
    int tx = threadIdx.x, ty = threadIdx.y;   // block (32, 8)
    #pragma unroll
    for (int i = 0; i < 32; i += 8)
        tile[ty + i][tx] = W[(by + ty + i) * DHID + bx + tx];
    __syncthreads();
    #pragma unroll
    for (int i = 0; i < 32; i += 8)
        Wt[(bx + ty + i) * KDIM + by + tx] = __float2half(tile[tx][ty + i]);
}

// ========================= CSR build =========================
__global__ void zero_deg_kernel() {
    int i = blockIdx.x * blockDim.x + threadIdx.x;
    if (i < N_NODES) g_deg[i] = 0;
}

__global__ void count_kernel(const int* __restrict__ ei) {
    int i = blockIdx.x * blockDim.x + threadIdx.x;
    if (i >= TOT_EDGES) return;
    int d = (i < N_EDGES) ? ei[N_EDGES + i] : (i - N_EDGES);
    atomicAdd(&g_deg[d], 1);
}

__global__ void block_reduce_kernel() {
    __shared__ int sh[256];
    int t = threadIdx.x;
    int i = blockIdx.x * 256 + t;
    sh[t] = (i < N_NODES) ? g_deg[i] : 0;
    __syncthreads();
    for (int o = 128; o > 0; o >>= 1) {
        if (t < o) sh[t] += sh[t + o];
        __syncthreads();
    }
    if (t == 0) g_blocksums[blockIdx.x] = sh[0];
}

__global__ void scan_blocks_kernel() {
    __shared__ int sh[256];
    int t = threadIdx.x;
    int v = (t < NBLK) ? g_blocksums[t] : 0;
    sh[t] = v;
    __syncthreads();
    for (int o = 1; o < 256; o <<= 1) {
        int x = (t >= o) ? sh[t - o] : 0;
        __syncthreads();
        sh[t] += x;
        __syncthreads();
    }
    if (t < NBLK) g_blocksums[t] = sh[t] - v;
}

__global__ void scatter_rowptr_kernel() {
    __shared__ int sh[256];
    int t = threadIdx.x;
    int i = blockIdx.x * 256 + t;
    int v = (i < N_NODES) ? g_deg[i] : 0;
    sh[t] = v;
    __syncthreads();
    for (int o = 1; o < 256; o <<= 1) {
        int x = (t >= o) ? sh[t - o] : 0;
        __syncthreads();
        sh[t] += x;
        __syncthreads();
    }
    int off = g_blocksums[blockIdx.x];
    if (i < N_NODES) {
        int r = off + sh[t] - v;
        g_rowptr[i] = r;
        g_cursor[i] = r;
        if (i == N_NODES - 1) g_rowptr[N_NODES] = TOT_EDGES;
    }
}

__global__ void fill_kernel(const int* __restrict__ ei) {
    int i = blockIdx.x * blockDim.x + threadIdx.x;
    if (i >= TOT_EDGES) return;
    int s, d;
    if (i < N_EDGES) { s = ei[i]; d = ei[N_EDGES + i]; }
    else             { s = d = i - N_EDGES; }
    int pos = atomicAdd(&g_cursor[d], 1);
    g_csr_src[pos] = s;
}

// ========================= fp16 GEMM + fused attn + fp16 store ===============
// BM=128, BN=128, BK=32; 8 warps (2x4), warp tile 64x32 (4x4 m16n8k16)
// A: [M][K] half row-major; B: Wt [N][K] half (col-major K x N for mma).
// layer: 0 -> A=g_x_half, B=g_w1t ; 1 -> A=g_act, B=g_w2t
#define BM 128
#define BN 128
#define BK 32
#define STRH 40     // halfs per row; conflict-free ldsm-free fragment loads

__global__ __launch_bounds__(256) void gemm_f16_kernel(
    int layer,
    const float* __restrict__ att_src, const float* __restrict__ att_dst)
{
    const __half* A  = layer ? (const __half*)g_act : (const __half*)g_x_half;
    const __half* Bt = layer ? (const __half*)g_w2t : (const __half*)g_w1t;

    __shared__ __half As[2][BM][STRH];
    __shared__ __half Bs[2][BN][STRH];
    float* s_attn = (float*)As;   // reused after MMA loop (4KB < 20KB)

    int bm = blockIdx.x * BM;
    int bn = blockIdx.y * BN;
    int tid  = threadIdx.x;
    int warp = tid >> 5;
    int lane = tid & 31;
    int wm = (warp & 1) * 64;
    int wn = (warp >> 1) * 32;
    int lr = lane >> 2;
    int lc = lane & 3;

    float c[4][4][4];
    #pragma unroll
    for (int mt = 0; mt < 4; mt++)
        #pragma unroll
        for (int nt = 0; nt < 4; nt++)
            #pragma unroll
            for (int f = 0; f < 4; f++) c[mt][nt][f] = 0.f;

    // tile loader: A tile 128x32 halfs = 512 x 16B; same for B
    auto load_tiles = [&](int st, int k0) {
        #pragma unroll
        for (int i = 0; i < 2; i++) {
            int idx = tid + i * 256;
            int r = idx >> 2;
            int cg = (idx & 3) * 8;    // halfs
            int gr = bm + r;
            int valid = (gr < N_NODES);
            int src_row = valid ? gr : 0;
            uint32_t dst = (uint32_t)__cvta_generic_to_shared(&As[st][r][cg]);
            cp_async16(dst, &A[(long)src_row * KDIM + k0 + cg], valid ? 16 : 0);
        }
        #pragma unroll
        for (int i = 0; i < 2; i++) {
            int idx = tid + i * 256;
            int r = idx >> 2;
            int cg = (idx & 3) * 8;
            uint32_t dst = (uint32_t)__cvta_generic_to_shared(&Bs[st][r][cg]);
            cp_async16(dst, &Bt[(long)(bn + r) * KDIM + k0 + cg], 16);
        }
        asm volatile("cp.async.commit_group;");
    };

    load_tiles(0, 0);

    const int NITER = KDIM / BK;   // 8
    #pragma unroll 1
    for (int it = 0; it < NITER; it++) {
        if (it + 1 < NITER) load_tiles((it + 1) & 1, (it + 1) * BK);
        if (it + 1 < NITER) asm volatile("cp.async.wait_group 1;");
        else                asm volatile("cp.async.wait_group 0;");
        __syncthreads();
        int st = it & 1;

        #pragma unroll
        for (int ks = 0; ks < 2; ks++) {
            int k = ks * 16;
            uint32_t af[4][4];
            #pragma unroll
            for (int mt = 0; mt < 4; mt++) {
                int r0 = wm + mt * 16 + lr;
                af[mt][0] = *(const uint32_t*)&As[st][r0][k + 2 * lc];
                af[mt][1] = *(const uint32_t*)&As[st][r0 + 8][k + 2 * lc];
                af[mt][2] = *(const uint32_t*)&As[st][r0][k + 2 * lc + 8];
                af[mt][3] = *(const uint32_t*)&As[st][r0 + 8][k + 2 * lc + 8];
            }
            uint32_t bf[4][2];
            #pragma unroll
            for (int nt = 0; nt < 4; nt++) {
                int col = wn + nt * 8 + lr;
                bf[nt][0] = *(const uint32_t*)&Bs[st][col][k + 2 * lc];
                bf[nt][1] = *(const uint32_t*)&Bs[st][col][k + 2 * lc + 8];
            }
            #pragma unroll
            for (int mt = 0; mt < 4; mt++)
                #pragma unroll
                for (int nt = 0; nt < 4; nt++) {
                    asm volatile(
                        "mma.sync.aligned.m16n8k16.row.col.f32.f16.f16.f32 "
                        "{%0,%1,%2,%3}, {%4,%5,%6,%7}, {%8,%9}, {%0,%1,%2,%3};"
                        : "+f"(c[mt][nt][0]), "+f"(c[mt][nt][1]),
                          "+f"(c[mt][nt][2]), "+f"(c[mt][nt][3])
                        : "r"(af[mt][0]), "r"(af[mt][1]), "r"(af[mt][2]), "r"(af[mt][3]),
                          "r"(bf[nt][0]), "r"(bf[nt][1]));
                }
        }
        __syncthreads();
    }

    // ---- store C as fp16 ----
    #pragma unroll
    for (int mt = 0; mt < 4; mt++) {
        int row0 = bm + wm + mt * 16 + lr;
        #pragma unroll
        for (int nt = 0; nt < 4; nt++) {
            int col = bn + wn + nt * 8 + 2 * lc;
            if (row0 < N_NODES)
                *(__half2*)&g_h_half[(long)row0 * DHID + col] =
                    __floats2half2_rn(c[mt][nt][0], c[mt][nt][1]);
            if (row0 + 8 < N_NODES)
                *(__half2*)&g_h_half[(long)(row0 + 8) * DHID + col] =
                    __floats2half2_rn(c[mt][nt][2], c[mt][nt][3]);
        }
    }

    // ---- fused attention scores (block owns heads 2*by, 2*by+1) ----
    int head_l = wn >> 6;
    int slot   = (wn >> 5) & 1;
    float attS[4][2], attD[4][2];
    #pragma unroll
    for (int nt = 0; nt < 4; nt++)
        #pragma unroll
        for (int j = 0; j < 2; j++) {
            int col = bn + wn + nt * 8 + 2 * lc + j;
            attS[nt][j] = att_src[col];
            attD[nt][j] = att_dst[col];
        }
    __syncthreads();   // all warps done with As before aliasing as s_attn
    #pragma unroll
    for (int mt = 0; mt < 4; mt++) {
        float s0 = 0.f, d0 = 0.f, s1 = 0.f, d1 = 0.f;
        #pragma unroll
        for (int nt = 0; nt < 4; nt++) {
            s0 += c[mt][nt][0] * attS[nt][0] + c[mt][nt][1] * attS[nt][1];
            d0 += c[mt][nt][0] * attD[nt][0] + c[mt][nt][1] * attD[nt][1];
            s1 += c[mt][nt][2] * attS[nt][0] + c[mt][nt][3] * attS[nt][1];
            d1 += c[mt][nt][2] * attD[nt][0] + c[mt][nt][3] * attD[nt][1];
        }
        #pragma unroll
        for (int o = 1; o < 4; o <<= 1) {
            s0 += __shfl_xor_sync(0xFFFFFFFFu, s0, o);
            d0 += __shfl_xor_sync(0xFFFFFFFFu, d0, o);
            s1 += __shfl_xor_sync(0xFFFFFFFFu, s1, o);
            d1 += __shfl_xor_sync(0xFFFFFFFFu, d1, o);
        }
        if (lc == 0) {
            int r0 = wm + mt * 16 + lr;
            s_attn[((0 * 2 + head_l) * 2 + slot) * BM + r0]     = s0;
            s_attn[((1 * 2 + head_l) * 2 + slot) * BM + r0]     = d0;
            s_attn[((0 * 2 + head_l) * 2 + slot) * BM + r0 + 8] = s1;
            s_attn[((1 * 2 + head_l) * 2 + slot) * BM + r0 + 8] = d1;
        }
    }
    __syncthreads();
    {
        int row = tid & 127;
        int hl  = tid >> 7;
        int node = bm + row;
        if (node < N_NODES) {
            int hg = blockIdx.y * 2 + hl;
            g_asrc[node * 4 + hg] = s_attn[((0 * 2 + hl) * 2 + 0) * BM + row]
                                  + s_attn[((0 * 2 + hl) * 2 + 1) * BM + row];
            g_adst[node * 4 + hg] = s_attn[((1 * 2 + hl) * 2 + 0) * BM + row]
                                  + s_attn[((1 * 2 + hl) * 2 + 1) * BM + row];
        }
    }
}

// ========================= fused aggregate (warp per node) ====================
__device__ __forceinline__ float4 eexp4(float4 a, float4 b) {
    float4 e;
    e.x = a.x + b.x; e.y = a.y + b.y; e.z = a.z + b.z; e.w = a.w + b.w;
    e.x = (e.x > 0.f) ? e.x : 0.2f * e.x;
    e.y = (e.y > 0.f) ? e.y : 0.2f * e.y;
    e.z = (e.z > 0.f) ? e.z : 0.2f * e.z;
    e.w = (e.w > 0.f) ? e.w : 0.2f * e.w;
    e.x = __expf(e.x); e.y = __expf(e.y); e.z = __expf(e.z); e.w = __expf(e.w);
    return e;
}

__device__ __forceinline__ void fma8(float* acc, float alpha, uint4 raw) {
    float2 f0 = __half22float2(*(__half2*)&raw.x);
    float2 f1 = __half22float2(*(__half2*)&raw.y);
    float2 f2 = __half22float2(*(__half2*)&raw.z);
    float2 f3 = __half22float2(*(__half2*)&raw.w);
    acc[0] += alpha * f0.x; acc[1] += alpha * f0.y;
    acc[2] += alpha * f1.x; acc[3] += alpha * f1.y;
    acc[4] += alpha * f2.x; acc[5] += alpha * f2.y;
    acc[6] += alpha * f3.x; acc[7] += alpha * f3.y;
}

__global__ __launch_bounds__(256) void gat_aggregate_kernel(
    const float* __restrict__ bias, float* __restrict__ dst_ext, int to_act)
{
    int n    = (blockIdx.x * blockDim.x + threadIdx.x) >> 5;
    int lane = threadIdx.x & 31;
    if (n >= N_NODES) return;
    int beg = g_rowptr[n];
    int end = g_rowptr[n + 1];
    float4 adst = *(const float4*)&g_adst[n * 4];

    // pass 1: denominator (strided over edges, 4 heads at once)
    float4 dsum = make_float4(0.f, 0.f, 0.f, 0.f);
    for (int e = beg + lane; e < end; e += 32) {
        int s = g_csr_src[e];
        float4 a = *(const float4*)&g_asrc[s * 4];
        float4 ee = eexp4(a, adst);
        dsum.x += ee.x; dsum.y += ee.y; dsum.z += ee.z; dsum.w += ee.w;
    }
    #pragma unroll
    for (int o = 16; o > 0; o >>= 1) {
        dsum.x += __shfl_xor_sync(0xFFFFFFFFu, dsum.x, o);
        dsum.y += __shfl_xor_sync(0xFFFFFFFFu, dsum.y, o);
        dsum.z += __shfl_xor_sync(0xFFFFFFFFu, dsum.z, o);
        dsum.w += __shfl_xor_sync(0xFFFFFFFFu, dsum.w, o);
    }
    int head = lane >> 3;
    float den = (head == 0) ? dsum.x : (head == 1) ? dsum.y : (head == 2) ? dsum.z : dsum.w;
    float inv = 1.f / (den + 1e-16f);
    float adst_h = (head == 0) ? adst.x : (head == 1) ? adst.y : (head == 2) ? adst.z : adst.w;

    // pass 2: scalar per-head score, unrolled x2 for MLP
    float acc[8] = {0.f, 0.f, 0.f, 0.f, 0.f, 0.f, 0.f, 0.f};
    int e = beg;
    for (; e + 2 <= end; e += 2) {
        int s0 = g_csr_src[e];
        int s1 = g_csr_src[e + 1];
        float a0 = __ldg(&g_asrc[s0 * 4 + head]);
        float a1 = __ldg(&g_asrc[s1 * 4 + head]);
        uint4 r0 = *(const uint4*)&g_h_half[(long)s0 * DHID + lane * 8];
        uint4 r1 = *(const uint4*)&g_h_half[(long)s1 * DHID + lane * 8];
        float e0 = a0 + adst_h; e0 = (e0 > 0.f) ? e0 : 0.2f * e0;
        float e1 = a1 + adst_h; e1 = (e1 > 0.f) ? e1 : 0.2f * e1;
        float al0 = __expf(e0) * inv;
        float al1 = __expf(e1) * inv;
        fma8(acc, al0, r0);
        fma8(acc, al1, r1);
    }
    if (e < end) {
        int s0 = g_csr_src[e];
        float a0 = __ldg(&g_asrc[s0 * 4 + head]);
        uint4 r0 = *(const uint4*)&g_h_half[(long)s0 * DHID + lane * 8];
        float e0 = a0 + adst_h; e0 = (e0 > 0.f) ? e0 : 0.2f * e0;
        fma8(acc, __expf(e0) * inv, r0);
    }

    // epilogue: bias + ELU + store
    float4 b0 = ((const float4*)bias)[lane * 2];
    float4 b1 = ((const float4*)bias)[lane * 2 + 1];
    float bb[8] = {b0.x, b0.y, b0.z, b0.w, b1.x, b1.y, b1.z, b1.w};
    #pragma unroll
    for (int i = 0; i < 8; i++) {
        float v = acc[i] + bb[i];
        acc[i] = (v > 0.f) ? v : expm1f(v);
    }
    if (to_act) {
        __half2 h0 = __floats2half2_rn(acc[0], acc[1]);
        __half2 h1 = __floats2half2_rn(acc[2], acc[3]);
        __half2 h2 = __floats2half2_rn(acc[4], acc[5]);
        __half2 h3 = __floats2half2_rn(acc[6], acc[7]);
        uint4 packed = make_uint4(*(uint32_t*)&h0, *(uint32_t*)&h1,
                                  *(uint32_t*)&h2, *(uint32_t*)&h3);
        *(uint4*)&g_act[(long)n * DHID + lane * 8] = packed;
    } else {
        float* op = &dst_ext[(long)n * DHID + lane * 8];
        *(float4*)op       = make_float4(acc[0], acc[1], acc[2], acc[3]);
        *(float4*)(op + 4) = make_float4(acc[4], acc[5], acc[6], acc[7]);
    }
}

// ========================= launch =========================
extern "C" void kernel_launch(void* const* d_in, const int* in_sizes, int n_in,
                              void* d_out, int out_size)
{
    const float* x   = (const float*)d_in[0];
    const int*   ei  = (const int*)  d_in[1];
    const float* W1  = (const float*)d_in[2];
    const float* as1 = (const float*)d_in[3];
    const float* ad1 = (const float*)d_in[4];
    const float* b1  = (const float*)d_in[5];
    const float* W2  = (const float*)d_in[6];
    const float* as2 = (const float*)d_in[7];
    const float* ad2 = (const float*)d_in[8];
    const float* b2  = (const float*)d_in[9];
    float* out = (float*)d_out;

    dim3 gemm_grid((N_NODES + BM - 1) / BM, DHID / BN);
    int edge_blocks = (TOT_EDGES + 255) / 256;
    int agg_blocks  = (N_NODES + 7) / 8;
    int cvtx_blocks = (N_NODES * KDIM / 8 + 255) / 256;

    // ---- input conversion ----
    convert_x_kernel<<<cvtx_blocks, 256>>>(x);
    dim3 wgrid(8, 8), wblk(32, 8);
    convert_w_kernel<<<wgrid, wblk>>>(W1, 0);
    convert_w_kernel<<<wgrid, wblk>>>(W2, 1);

    // ---- CSR build ----
    zero_deg_kernel<<<NBLK, 256>>>();
    count_kernel<<<edge_blocks, 256>>>(ei);
    block_reduce_kernel<<<NBLK, 256>>>();
    scan_blocks_kernel<<<1, 256>>>();
    scatter_rowptr_kernel<<<NBLK, 256>>>();
    fill_kernel<<<edge_blocks, 256>>>(ei);

    // ---- layer 1 ----
    gemm_f16_kernel<<<gemm_grid, 256>>>(0, as1, ad1);
    gat_aggregate_kernel<<<agg_blocks, 256>>>(b1, nullptr, 1);

    // ---- layer 2 ----
    gemm_f16_kernel<<<gemm_grid, 256>>>(1, as2, ad2);
    gat_aggregate_kernel<<<agg_blocks, 256>>>(b2, out, 0);
}

// round 7
// speedup vs baseline: 4.1799x; 1.0630x over previous
#include <cuda_runtime.h>
#include <cuda_fp16.h>
#include <math.h>
#include <stdint.h>

#define N_NODES   50000
#define N_EDGES   800000
#define TOT_EDGES (N_EDGES + N_NODES)
#define HEADS     4
#define OUT_CH    64
#define DHID      256
#define KDIM      256
#define NBLK      196        // ceil(N_NODES/256)

// ---------------- scratch (static device globals; no allocation) ------------
__device__ __half g_h_half[N_NODES * DHID];   // fp16 features for gather
__device__ __half g_act[N_NODES * DHID];      // layer-1 output after ELU (half)
__device__ __half g_x_half[N_NODES * KDIM];   // fp16 copy of input x
__device__ __half g_w1t[DHID * KDIM];         // W1^T in half: [n][k]
__device__ __half g_w2t[DHID * KDIM];         // W2^T in half
__device__ float  g_asrc[N_NODES * HEADS];
__device__ float  g_adst[N_NODES * HEADS];
__device__ int    g_deg[N_NODES];
__device__ int    g_rowptr[N_NODES + 1];
__device__ int    g_cursor[N_NODES];
__device__ int    g_csr_src[TOT_EDGES];
__device__ int    g_blocksums[256];

// ---------------- streams/events (created at load time, before harness
// checkpoints; never allocated inside kernel_launch) ------------------------
struct GraphStreams {
    cudaStream_t s2 = nullptr;
    cudaEvent_t ev0 = nullptr, evX = nullptr, evG1 = nullptr;
    GraphStreams() {
        cudaStreamCreateWithFlags(&s2, cudaStreamNonBlocking);
        cudaEventCreateWithFlags(&ev0, cudaEventDisableTiming);
        cudaEventCreateWithFlags(&evX, cudaEventDisableTiming);
        cudaEventCreateWithFlags(&evG1, cudaEventDisableTiming);
    }
};
static GraphStreams g_gs;

__device__ __forceinline__ void cp_async16(uint32_t smem_dst, const void* gsrc, int src_bytes) {
    asm volatile("cp.async.cg.shared.global [%0], [%1], 16, %2;"
                 :: "r"(smem_dst), "l"(gsrc), "r"(src_bytes));
}

// ========================= input conversion (+ deg zero) =====================
__global__ void convert_x_kernel(const float* __restrict__ x) {
    int i = blockIdx.x * blockDim.x + threadIdx.x;
    const int TOT8 = N_NODES * KDIM / 8;
    if (i < N_NODES) g_deg[i] = 0;           // fused zero_deg
    if (i >= TOT8) return;
    float4 v0 = ((const float4*)x)[2 * i];
    float4 v1 = ((const float4*)x)[2 * i + 1];
    __half2 h0 = __floats2half2_rn(v0.x, v0.y);
    __half2 h1 = __floats2half2_rn(v0.z, v0.w);
    __half2 h2 = __floats2half2_rn(v1.x, v1.y);
    __half2 h3 = __floats2half2_rn(v1.z, v1.w);
    uint4 packed = make_uint4(*(uint32_t*)&h0, *(uint32_t*)&h1,
                              *(uint32_t*)&h2, *(uint32_t*)&h3);
    ((uint4*)g_x_half)[i] = packed;
}

// transpose + convert both W [K][N] fp32 -> Wt [N][K] half (32x32 tiles)
// blockIdx.z selects weight 0/1
__global__ void convert_w_kernel(const float* __restrict__ W1,
                                 const float* __restrict__ W2) {
    const float* W = blockIdx.z ? W2 : W1;
    __half* Wt = blockIdx.z ? g_w2t : g_w1t;
    __shared__ float tile[32][33];
    int bx = blockIdx.x * 32, by = blockIdx.y * 32;
    int tx = threadIdx.x, ty = threadIdx.y;   // block (32, 8)
    #pragma unroll
    for (int i = 0; i < 32; i += 8)
        tile[ty + i][tx] = W[(by + ty + i) * DHID + bx + tx];
    __syncthreads();
    #pragma unroll
    for (int i = 0; i < 32; i += 8)
        Wt[(bx + ty + i) * KDIM + by + tx] = __float2half(tile[tx][ty + i]);
}

// ========================= CSR build =========================
__global__ void count_kernel(const int* __restrict__ ei) {
    int i = blockIdx.x * blockDim.x + threadIdx.x;
    if (i >= TOT_EDGES) return;
    int d = (i < N_EDGES) ? ei[N_EDGES + i] : (i - N_EDGES);
    atomicAdd(&g_deg[d], 1);
}

__global__ void block_reduce_kernel() {
    __shared__ int sh[256];
    int t = threadIdx.x;
    int i = blockIdx.x * 256 + t;
    sh[t] = (i < N_NODES) ? g_deg[i] : 0;
    __syncthreads();
    for (int o = 128; o > 0; o >>= 1) {
        if (t < o) sh[t] += sh[t + o];
        __syncthreads();
    }
    if (t == 0) g_blocksums[blockIdx.x] = sh[0];
}

__global__ void scan_blocks_kernel() {
    __shared__ int sh[256];
    int t = threadIdx.x;
    int v = (t < NBLK) ? g_blocksums[t] : 0;
    sh[t] = v;
    __syncthreads();
    for (int o = 1; o < 256; o <<= 1) {
        int x = (t >= o) ? sh[t - o] : 0;
        __syncthreads();
        sh[t] += x;
        __syncthreads();
    }
    if (t < NBLK) g_blocksums[t] = sh[t] - v;
}

__global__ void scatter_rowptr_kernel() {
    __shared__ int sh[256];
    int t = threadIdx.x;
    int i = blockIdx.x * 256 + t;
    int v = (i < N_NODES) ? g_deg[i] : 0;
    sh[t] = v;
    __syncthreads();
    for (int o = 1; o < 256; o <<= 1) {
        int x = (t >= o) ? sh[t - o] : 0;
        __syncthreads();
        sh[t] += x;
        __syncthreads();
    }
    int off = g_blocksums[blockIdx.x];
    if (i < N_NODES) {
        int r = off + sh[t] - v;
        g_rowptr[i] = r;
        g_cursor[i] = r;
        if (i == N_NODES - 1) g_rowptr[N_NODES] = TOT_EDGES;
    }
}

__global__ void fill_kernel(const int* __restrict__ ei) {
    int i = blockIdx.x * blockDim.x + threadIdx.x;
    if (i >= TOT_EDGES) return;
    int s, d;
    if (i < N_EDGES) { s = ei[i]; d = ei[N_EDGES + i]; }
    else             { s = d = i - N_EDGES; }
    int pos = atomicAdd(&g_cursor[d], 1);
    g_csr_src[pos] = s;
}

// ========================= fp16 GEMM + fused attn + fp16 store ===============
#define BM 128
#define BN 128
#define BK 32
#define STRH 40

__global__ __launch_bounds__(256) void gemm_f16_kernel(
    int layer,
    const float* __restrict__ att_src, const float* __restrict__ att_dst)
{
    const __half* A  = layer ? (const __half*)g_act : (const __half*)g_x_half;
    const __half* Bt = layer ? (const __half*)g_w2t : (const __half*)g_w1t;

    __shared__ __half As[2][BM][STRH];
    __shared__ __half Bs[2][BN][STRH];
    float* s_attn = (float*)As;

    int bm = blockIdx.x * BM;
    int bn = blockIdx.y * BN;
    int tid  = threadIdx.x;
    int warp = tid >> 5;
    int lane = tid & 31;
    int wm = (warp & 1) * 64;
    int wn = (warp >> 1) * 32;
    int lr = lane >> 2;
    int lc = lane & 3;

    float c[4][4][4];
    #pragma unroll
    for (int mt = 0; mt < 4; mt++)
        #pragma unroll
        for (int nt = 0; nt < 4; nt++)
            #pragma unroll
            for (int f = 0; f < 4; f++) c[mt][nt][f] = 0.f;

    auto load_tiles = [&](int st, int k0) {
        #pragma unroll
        for (int i = 0; i < 2; i++) {
            int idx = tid + i * 256;
            int r = idx >> 2;
            int cg = (idx & 3) * 8;
            int gr = bm + r;
            int valid = (gr < N_NODES);
            int src_row = valid ? gr : 0;
            uint32_t dst = (uint32_t)__cvta_generic_to_shared(&As[st][r][cg]);
            cp_async16(dst, &A[(long)src_row * KDIM + k0 + cg], valid ? 16 : 0);
        }
        #pragma unroll
        for (int i = 0; i < 2; i++) {
            int idx = tid + i * 256;
            int r = idx >> 2;
            int cg = (idx & 3) * 8;
            uint32_t dst = (uint32_t)__cvta_generic_to_shared(&Bs[st][r][cg]);
            cp_async16(dst, &Bt[(long)(bn + r) * KDIM + k0 + cg], 16);
        }
        asm volatile("cp.async.commit_group;");
    };

    load_tiles(0, 0);

    const int NITER = KDIM / BK;   // 8
    #pragma unroll 1
    for (int it = 0; it < NITER; it++) {
        if (it + 1 < NITER) load_tiles((it + 1) & 1, (it + 1) * BK);
        if (it + 1 < NITER) asm volatile("cp.async.wait_group 1;");
        else                asm volatile("cp.async.wait_group 0;");
        __syncthreads();
        int st = it & 1;

        #pragma unroll
        for (int ks = 0; ks < 2; ks++) {
            int k = ks * 16;
            uint32_t af[4][4];
            #pragma unroll
            for (int mt = 0; mt < 4; mt++) {
                int r0 = wm + mt * 16 + lr;
                af[mt][0] = *(const uint32_t*)&As[st][r0][k + 2 * lc];
                af[mt][1] = *(const uint32_t*)&As[st][r0 + 8][k + 2 * lc];
                af[mt][2] = *(const uint32_t*)&As[st][r0][k + 2 * lc + 8];
                af[mt][3] = *(const uint32_t*)&As[st][r0 + 8][k + 2 * lc + 8];
            }
            uint32_t bf[4][2];
            #pragma unroll
            for (int nt = 0; nt < 4; nt++) {
                int col = wn + nt * 8 + lr;
                bf[nt][0] = *(const uint32_t*)&Bs[st][col][k + 2 * lc];
                bf[nt][1] = *(const uint32_t*)&Bs[st][col][k + 2 * lc + 8];
            }
            #pragma unroll
            for (int mt = 0; mt < 4; mt++)
                #pragma unroll
                for (int nt = 0; nt < 4; nt++) {
                    asm volatile(
                        "mma.sync.aligned.m16n8k16.row.col.f32.f16.f16.f32 "
                        "{%0,%1,%2,%3}, {%4,%5,%6,%7}, {%8,%9}, {%0,%1,%2,%3};"
                        : "+f"(c[mt][nt][0]), "+f"(c[mt][nt][1]),
                          "+f"(c[mt][nt][2]), "+f"(c[mt][nt][3])
                        : "r"(af[mt][0]), "r"(af[mt][1]), "r"(af[mt][2]), "r"(af[mt][3]),
                          "r"(bf[nt][0]), "r"(bf[nt][1]));
                }
        }
        __syncthreads();
    }

    // ---- store C as fp16 ----
    #pragma unroll
    for (int mt = 0; mt < 4; mt++) {
        int row0 = bm + wm + mt * 16 + lr;
        #pragma unroll
        for (int nt = 0; nt < 4; nt++) {
            int col = bn + wn + nt * 8 + 2 * lc;
            if (row0 < N_NODES)
                *(__half2*)&g_h_half[(long)row0 * DHID + col] =
                    __floats2half2_rn(c[mt][nt][0], c[mt][nt][1]);
            if (row0 + 8 < N_NODES)
                *(__half2*)&g_h_half[(long)(row0 + 8) * DHID + col] =
                    __floats2half2_rn(c[mt][nt][2], c[mt][nt][3]);
        }
    }

    // ---- fused attention scores (block owns heads 2*by, 2*by+1) ----
    int head_l = wn >> 6;
    int slot   = (wn >> 5) & 1;
    float attS[4][2], attD[4][2];
    #pragma unroll
    for (int nt = 0; nt < 4; nt++)
        #pragma unroll
        for (int j = 0; j < 2; j++) {
            int col = bn + wn + nt * 8 + 2 * lc + j;
            attS[nt][j] = att_src[col];
            attD[nt][j] = att_dst[col];
        }
    __syncthreads();
    #pragma unroll
    for (int mt = 0; mt < 4; mt++) {
        float s0 = 0.f, d0 = 0.f, s1 = 0.f, d1 = 0.f;
        #pragma unroll
        for (int nt = 0; nt < 4; nt++) {
            s0 += c[mt][nt][0] * attS[nt][0] + c[mt][nt][1] * attS[nt][1];
            d0 += c[mt][nt][0] * attD[nt][0] + c[mt][nt][1] * attD[nt][1];
            s1 += c[mt][nt][2] * attS[nt][0] + c[mt][nt][3] * attS[nt][1];
            d1 += c[mt][nt][2] * attD[nt][0] + c[mt][nt][3] * attD[nt][1];
        }
        #pragma unroll
        for (int o = 1; o < 4; o <<= 1) {
            s0 += __shfl_xor_sync(0xFFFFFFFFu, s0, o);
            d0 += __shfl_xor_sync(0xFFFFFFFFu, d0, o);
            s1 += __shfl_xor_sync(0xFFFFFFFFu, s1, o);
            d1 += __shfl_xor_sync(0xFFFFFFFFu, d1, o);
        }
        if (lc == 0) {
            int r0 = wm + mt * 16 + lr;
            s_attn[((0 * 2 + head_l) * 2 + slot) * BM + r0]     = s0;
            s_attn[((1 * 2 + head_l) * 2 + slot) * BM + r0]     = d0;
            s_attn[((0 * 2 + head_l) * 2 + slot) * BM + r0 + 8] = s1;
            s_attn[((1 * 2 + head_l) * 2 + slot) * BM + r0 + 8] = d1;
        }
    }
    __syncthreads();
    {
        int row = tid & 127;
        int hl  = tid >> 7;
        int node = bm + row;
        if (node < N_NODES) {
            int hg = blockIdx.y * 2 + hl;
            g_asrc[node * 4 + hg] = s_attn[((0 * 2 + hl) * 2 + 0) * BM + row]
                                  + s_attn[((0 * 2 + hl) * 2 + 1) * BM + row];
            g_adst[node * 4 + hg] = s_attn[((1 * 2 + hl) * 2 + 0) * BM + row]
                                  + s_attn[((1 * 2 + hl) * 2 + 1) * BM + row];
        }
    }
}

// ========================= fused aggregate (warp per node) ====================
__device__ __forceinline__ float4 eexp4(float4 a, float4 b) {
    float4 e;
    e.x = a.x + b.x; e.y = a.y + b.y; e.z = a.z + b.z; e.w = a.w + b.w;
    e.x = (e.x > 0.f) ? e.x : 0.2f * e.x;
    e.y = (e.y > 0.f) ? e.y : 0.2f * e.y;
    e.z = (e.z > 0.f) ? e.z : 0.2f * e.z;
    e.w = (e.w > 0.f) ? e.w : 0.2f * e.w;
    e.x = __expf(e.x); e.y = __expf(e.y); e.z = __expf(e.z); e.w = __expf(e.w);
    return e;
}

__device__ __forceinline__ void fma8(float* acc, float alpha, uint4 raw) {
    float2 f0 = __half22float2(*(__half2*)&raw.x);
    float2 f1 = __half22float2(*(__half2*)&raw.y);
    float2 f2 = __half22float2(*(__half2*)&raw.z);
    float2 f3 = __half22float2(*(__half2*)&raw.w);
    acc[0] += alpha * f0.x; acc[1] += alpha * f0.y;
    acc[2] += alpha * f1.x; acc[3] += alpha * f1.y;
    acc[4] += alpha * f2.x; acc[5] += alpha * f2.y;
    acc[6] += alpha * f3.x; acc[7] += alpha * f3.y;
}

__global__ __launch_bounds__(256) void gat_aggregate_kernel(
    const float* __restrict__ bias, float* __restrict__ dst_ext, int to_act)
{
    int n    = (blockIdx.x * blockDim.x + threadIdx.x) >> 5;
    int lane = threadIdx.x & 31;
    if (n >= N_NODES) return;
    int beg = g_rowptr[n];
    int end = g_rowptr[n + 1];
    float4 adst = *(const float4*)&g_adst[n * 4];

    // pass 1: denominator (strided over edges, 4 heads at once)
    float4 dsum = make_float4(0.f, 0.f, 0.f, 0.f);
    for (int e = beg + lane; e < end; e += 32) {
        int s = g_csr_src[e];
        float4 a = *(const float4*)&g_asrc[s * 4];
        float4 ee = eexp4(a, adst);
        dsum.x += ee.x; dsum.y += ee.y; dsum.z += ee.z; dsum.w += ee.w;
    }
    #pragma unroll
    for (int o = 16; o > 0; o >>= 1) {
        dsum.x += __shfl_xor_sync(0xFFFFFFFFu, dsum.x, o);
        dsum.y += __shfl_xor_sync(0xFFFFFFFFu, dsum.y, o);
        dsum.z += __shfl_xor_sync(0xFFFFFFFFu, dsum.z, o);
        dsum.w += __shfl_xor_sync(0xFFFFFFFFu, dsum.w, o);
    }
    int head = lane >> 3;
    float den = (head == 0) ? dsum.x : (head == 1) ? dsum.y : (head == 2) ? dsum.z : dsum.w;
    float inv = 1.f / (den + 1e-16f);
    float adst_h = (head == 0) ? adst.x : (head == 1) ? adst.y : (head == 2) ? adst.z : adst.w;

    // pass 2: scalar per-head score, unrolled x4 for MLP
    float acc[8] = {0.f, 0.f, 0.f, 0.f, 0.f, 0.f, 0.f, 0.f};
    int e = beg;
    for (; e + 4 <= end; e += 4) {
        int i0 = g_csr_src[e];
        int i1 = g_csr_src[e + 1];
        int i2 = g_csr_src[e + 2];
        int i3 = g_csr_src[e + 3];
        float a0 = __ldg(&g_asrc[i0 * 4 + head]);
        float a1 = __ldg(&g_asrc[i1 * 4 + head]);
        float a2 = __ldg(&g_asrc[i2 * 4 + head]);
        float a3 = __ldg(&g_asrc[i3 * 4 + head]);
        uint4 r0 = *(const uint4*)&g_h_half[(long)i0 * DHID + lane * 8];
        uint4 r1 = *(const uint4*)&g_h_half[(long)i1 * DHID + lane * 8];
        uint4 r2 = *(const uint4*)&g_h_half[(long)i2 * DHID + lane * 8];
        uint4 r3 = *(const uint4*)&g_h_half[(long)i3 * DHID + lane * 8];
        float e0 = a0 + adst_h; e0 = (e0 > 0.f) ? e0 : 0.2f * e0;
        float e1 = a1 + adst_h; e1 = (e1 > 0.f) ? e1 : 0.2f * e1;
        float e2 = a2 + adst_h; e2 = (e2 > 0.f) ? e2 : 0.2f * e2;
        float e3 = a3 + adst_h; e3 = (e3 > 0.f) ? e3 : 0.2f * e3;
        fma8(acc, __expf(e0) * inv, r0);
        fma8(acc, __expf(e1) * inv, r1);
        fma8(acc, __expf(e2) * inv, r2);
        fma8(acc, __expf(e3) * inv, r3);
    }
    for (; e < end; e++) {
        int i0 = g_csr_src[e];
        float a0 = __ldg(&g_asrc[i0 * 4 + head]);
        uint4 r0 = *(const uint4*)&g_h_half[(long)i0 * DHID + lane * 8];
        float e0 = a0 + adst_h; e0 = (e0 > 0.f) ? e0 : 0.2f * e0;
        fma8(acc, __expf(e0) * inv, r0);
    }

    // epilogue: bias + ELU + store
    float4 b0 = ((const float4*)bias)[lane * 2];
    float4 b1 = ((const float4*)bias)[lane * 2 + 1];
    float bb[8] = {b0.x, b0.y, b0.z, b0.w, b1.x, b1.y, b1.z, b1.w};
    #pragma unroll
    for (int i = 0; i < 8; i++) {
        float v = acc[i] + bb[i];
        acc[i] = (v > 0.f) ? v : expm1f(v);
    }
    if (to_act) {
        __half2 h0 = __floats2half2_rn(acc[0], acc[1]);
        __half2 h1 = __floats2half2_rn(acc[2], acc[3]);
        __half2 h2 = __floats2half2_rn(acc[4], acc[5]);
        __half2 h3 = __floats2half2_rn(acc[6], acc[7]);
        uint4 packed = make_uint4(*(uint32_t*)&h0, *(uint32_t*)&h1,
                                  *(uint32_t*)&h2, *(uint32_t*)&h3);
        *(uint4*)&g_act[(long)n * DHID + lane * 8] = packed;
    } else {
        float* op = &dst_ext[(long)n * DHID + lane * 8];
        *(float4*)op       = make_float4(acc[0], acc[1], acc[2], acc[3]);
        *(float4*)(op + 4) = make_float4(acc[4], acc[5], acc[6], acc[7]);
    }
}

// ========================= launch =========================
extern "C" void kernel_launch(void* const* d_in, const int* in_sizes, int n_in,
                              void* d_out, int out_size)
{
    const float* x   = (const float*)d_in[0];
    const int*   ei  = (const int*)  d_in[1];
    const float* W1  = (const float*)d_in[2];
    const float* as1 = (const float*)d_in[3];
    const float* ad1 = (const float*)d_in[4];
    const float* b1  = (const float*)d_in[5];
    const float* W2  = (const float*)d_in[6];
    const float* as2 = (const float*)d_in[7];
    const float* ad2 = (const float*)d_in[8];
    const float* b2  = (const float*)d_in[9];
    float* out = (float*)d_out;

    cudaStream_t s0 = 0;           // legacy default (the captured stream)
    cudaStream_t s2 = g_gs.s2;

    dim3 gemm_grid((N_NODES + BM - 1) / BM, DHID / BN);
    int edge_blocks = (TOT_EDGES + 255) / 256;
    int agg_blocks  = (N_NODES + 7) / 8;
    int cvtx_blocks = (N_NODES * KDIM / 8 + 255) / 256;
    dim3 wgrid(8, 8, 2), wblk(32, 8);

    // fork point
    cudaEventRecord(g_gs.ev0, s0);
    cudaStreamWaitEvent(s2, g_gs.ev0, 0);

    // ---- s0: convert x (+zero deg), then CSR build ----
    convert_x_kernel<<<cvtx_blocks, 256, 0, s0>>>(x);
    cudaEventRecord(g_gs.evX, s0);
    count_kernel<<<edge_blocks, 256, 0, s0>>>(ei);
    block_reduce_kernel<<<NBLK, 256, 0, s0>>>();
    scan_blocks_kernel<<<1, 256, 0, s0>>>();
    scatter_rowptr_kernel<<<NBLK, 256, 0, s0>>>();
    fill_kernel<<<edge_blocks, 256, 0, s0>>>(ei);

    // ---- s2: weights + layer-1 GEMM (needs x conversion) ----
    convert_w_kernel<<<wgrid, wblk, 0, s2>>>(W1, W2);
    cudaStreamWaitEvent(s2, g_gs.evX, 0);
    gemm_f16_kernel<<<gemm_grid, 256, 0, s2>>>(0, as1, ad1);
    cudaEventRecord(g_gs.evG1, s2);

    // ---- s0: join, then the serial tail ----
    cudaStreamWaitEvent(s0, g_gs.evG1, 0);
    gat_aggregate_kernel<<<agg_blocks, 256, 0, s0>>>(b1, nullptr, 1);
    gemm_f16_kernel<<<gemm_grid, 256, 0, s0>>>(1, as2, ad2);
    gat_aggregate_kernel<<<agg_blocks, 256, 0, s0>>>(b2, out, 0);
}